// round 2
// baseline (speedup 1.0000x reference)
#include <cuda_runtime.h>
#include <cuda_bf16.h>
#include <math.h>

// ---------------- problem constants ----------------
#define BB 32
#define NN 1369
#define DD 768
#define KK 12
#define TT 3
#define HH 8
#define HD 96
#define BNROWS (BB * NN)          // 43808
#define SROWS  (BB * KK)          // 384
#define SCALE_QK 0.03608439182435161f   // 768^-0.5
#define SCALE_HD 0.10206207261596575f   // 96^-0.5

// ---------------- scratch (device globals, no allocation) ----------------
__device__ float g_fn  [(size_t)BNROWS * DD];
__device__ float g_kmat[(size_t)BNROWS * DD];
__device__ float g_vmat[(size_t)BNROWS * DD];
__device__ float g_attn[(size_t)BNROWS * KK];
__device__ float g_sn  [(size_t)SROWS * DD];
__device__ float g_q   [(size_t)SROWS * DD];
__device__ float g_mass[SROWS];
__device__ float g_upd [(size_t)SROWS * DD];
__device__ float g_h1  [(size_t)SROWS * DD];
__device__ float g_qkv [(size_t)SROWS * 3 * DD];
__device__ float g_o   [(size_t)SROWS * DD];
__device__ float g_x1  [(size_t)SROWS * DD];
__device__ float g_h2  [(size_t)SROWS * DD];
__device__ float g_g1  [(size_t)SROWS * 4 * DD];
__device__ float g_x2  [(size_t)SROWS * DD];
__device__ float g_h3  [(size_t)SROWS * DD];
__device__ float g_g2  [(size_t)SROWS * 4 * DD];
__device__ float g_slots[(size_t)SROWS * DD];

// ---------------- helpers ----------------
__device__ __forceinline__ float gelu_exact(float x) {
    return 0.5f * x * (1.0f + erff(x * 0.70710678118654752f));
}

// ---------------- LayerNorm: out = LN(x [+ x2]) * g + b ; row length 768 ----------------
__global__ void ln_kernel(const float* __restrict__ x, const float* __restrict__ x2,
                          const float* __restrict__ gam, const float* __restrict__ bet,
                          float* __restrict__ out) {
    int r = blockIdx.x;
    int tid = threadIdx.x;
    const float* xr = x + (size_t)r * DD;
    const float* x2r = x2 ? (x2 + (size_t)r * DD) : nullptr;
    float v[3];
    float s = 0.f;
#pragma unroll
    for (int i = 0; i < 3; i++) {
        int d = tid + i * 256;
        float t = xr[d];
        if (x2r) t += x2r[d];
        v[i] = t;
        s += t;
    }
    __shared__ float red[256];
    red[tid] = s;
    __syncthreads();
    for (int off = 128; off > 0; off >>= 1) {
        if (tid < off) red[tid] += red[tid + off];
        __syncthreads();
    }
    float mean = red[0] * (1.0f / DD);
    __syncthreads();
    float s2 = 0.f;
#pragma unroll
    for (int i = 0; i < 3; i++) { float dl = v[i] - mean; s2 += dl * dl; }
    red[tid] = s2;
    __syncthreads();
    for (int off = 128; off > 0; off >>= 1) {
        if (tid < off) red[tid] += red[tid + off];
        __syncthreads();
    }
    float inv = rsqrtf(red[0] * (1.0f / DD) + 1e-5f);
#pragma unroll
    for (int i = 0; i < 3; i++) {
        int d = tid + i * 256;
        out[(size_t)r * DD + d] = (v[i] - mean) * inv * gam[d] + bet[d];
    }
}

// ---------------- generic tiled fp32 GEMM: C = act(A@W + bias) + add ----------------
// A:[M,Kc] row-major, W:[Kc,Nc] row-major, C:[M,Nc]. Nc % 64 == 0, Kc % 16 == 0.
__global__ void gemm_kernel(const float* __restrict__ A, const float* __restrict__ W,
                            const float* __restrict__ bias, const float* __restrict__ addsrc,
                            float* __restrict__ C, int M, int Nc, int Kc, int act) {
    __shared__ float As[16][64];
    __shared__ float Ws[16][64];
    int bm = blockIdx.y * 64, bn = blockIdx.x * 64;
    int tid = threadIdx.x;
    int tx = tid % 16, ty = tid / 16;
    float acc[4][4] = {};
    for (int k0 = 0; k0 < Kc; k0 += 16) {
#pragma unroll
        for (int i = 0; i < 4; i++) {
            int idx = tid + i * 256;           // 0..1023
            int r = idx >> 4, c = idx & 15;    // A tile [64 x 16]
            int gm = bm + r;
            As[c][r] = (gm < M) ? A[(size_t)gm * Kc + k0 + c] : 0.f;
        }
#pragma unroll
        for (int i = 0; i < 4; i++) {
            int idx = tid + i * 256;
            int r = idx >> 6, c = idx & 63;    // W tile [16 x 64]
            Ws[r][c] = W[(size_t)(k0 + r) * Nc + bn + c];
        }
        __syncthreads();
#pragma unroll
        for (int kk = 0; kk < 16; kk++) {
            float4 a4 = *(const float4*)&As[kk][ty * 4];
            float4 w4 = *(const float4*)&Ws[kk][tx * 4];
            float a[4] = {a4.x, a4.y, a4.z, a4.w};
            float w[4] = {w4.x, w4.y, w4.z, w4.w};
#pragma unroll
            for (int i = 0; i < 4; i++)
#pragma unroll
                for (int j = 0; j < 4; j++)
                    acc[i][j] = fmaf(a[i], w[j], acc[i][j]);
        }
        __syncthreads();
    }
#pragma unroll
    for (int i = 0; i < 4; i++) {
        int gm = bm + ty * 4 + i;
        if (gm >= M) continue;
#pragma unroll
        for (int j = 0; j < 4; j++) {
            int gn = bn + tx * 4 + j;
            float vres = acc[i][j];
            if (bias) vres += bias[gn];
            if (act) vres = gelu_exact(vres);
            if (addsrc) vres += addsrc[(size_t)gm * Nc + gn];
            C[(size_t)gm * Nc + gn] = vres;
        }
    }
}

// ---------------- slot<-feature logits + competitive softmax over K ----------------
// attn[b,n,k] = softmax_k( SCALE * q[b,k,:] . kmat[b,n,:] )
__global__ void qk_softmax_kernel(const float* __restrict__ q, const float* __restrict__ kmat,
                                  float* __restrict__ attn) {
    __shared__ float qs[KK][DD];   // 36 KB
    int b = blockIdx.x;
    int tid = threadIdx.x;
    const float* qb = q + (size_t)b * KK * DD;
    for (int i = tid; i < KK * DD; i += 256) qs[i / DD][i % DD] = qb[i];
    __syncthreads();
    int w = tid >> 5, lane = tid & 31;
    int n = blockIdx.y * 8 + w;
    if (n >= NN) return;
    const float* kr = kmat + ((size_t)b * NN + n) * DD;
    float p[KK];
#pragma unroll
    for (int s = 0; s < KK; s++) p[s] = 0.f;
    for (int d = lane; d < DD; d += 32) {
        float kv = kr[d];
#pragma unroll
        for (int s = 0; s < KK; s++) p[s] = fmaf(kv, qs[s][d], p[s]);
    }
#pragma unroll
    for (int s = 0; s < KK; s++)
        for (int off = 16; off; off >>= 1) p[s] += __shfl_xor_sync(0xffffffffu, p[s], off);
    float mx = -1e30f;
#pragma unroll
    for (int s = 0; s < KK; s++) { p[s] *= SCALE_QK; mx = fmaxf(mx, p[s]); }
    float tot = 0.f;
    float e[KK];
#pragma unroll
    for (int s = 0; s < KK; s++) { e[s] = expf(p[s] - mx); tot += e[s]; }
    float invt = 1.0f / tot;
    if (lane < KK) attn[((size_t)b * NN + n) * KK + lane] = e[lane] * invt;
}

// ---------------- mass[b,k] = max(sum_n attn[b,n,k], 1e-8) ----------------
__global__ void mass_kernel(const float* __restrict__ attn, float* __restrict__ mass) {
    int b = blockIdx.x, tid = threadIdx.x;
    float acc[KK];
#pragma unroll
    for (int s = 0; s < KK; s++) acc[s] = 0.f;
    for (int n = tid; n < NN; n += 256) {
        const float4* ar = (const float4*)(attn + ((size_t)b * NN + n) * KK);
        float4 a0 = ar[0], a1 = ar[1], a2 = ar[2];
        acc[0] += a0.x; acc[1] += a0.y; acc[2]  += a0.z; acc[3]  += a0.w;
        acc[4] += a1.x; acc[5] += a1.y; acc[6]  += a1.z; acc[7]  += a1.w;
        acc[8] += a2.x; acc[9] += a2.y; acc[10] += a2.z; acc[11] += a2.w;
    }
    __shared__ float red[KK][257];
#pragma unroll
    for (int s = 0; s < KK; s++) red[s][tid] = acc[s];
    __syncthreads();
    for (int off = 128; off > 0; off >>= 1) {
        if (tid < off)
#pragma unroll
            for (int s = 0; s < KK; s++) red[s][tid] += red[s][tid + off];
        __syncthreads();
    }
    if (tid < KK) mass[b * KK + tid] = fmaxf(red[tid][0], 1e-8f);
}

// ---------------- updates[b,k,d] = (sum_n attn[b,n,k]*v[b,n,d]) / mass[b,k] ----------------
__global__ void updates_kernel(const float* __restrict__ attn, const float* __restrict__ v,
                               const float* __restrict__ mass, float* __restrict__ upd) {
    int b = blockIdx.x;
    int d = blockIdx.y * 128 + threadIdx.x;
    const float* vb = v + (size_t)b * NN * DD;
    const float* ab = attn + (size_t)b * NN * KK;
    float acc[KK];
#pragma unroll
    for (int s = 0; s < KK; s++) acc[s] = 0.f;
    for (int n = 0; n < NN; n++) {
        float vv = vb[(size_t)n * DD + d];
        const float4* ar = (const float4*)(ab + (size_t)n * KK);
        float4 a0 = ar[0], a1 = ar[1], a2 = ar[2];
        acc[0]  = fmaf(a0.x, vv, acc[0]);  acc[1]  = fmaf(a0.y, vv, acc[1]);
        acc[2]  = fmaf(a0.z, vv, acc[2]);  acc[3]  = fmaf(a0.w, vv, acc[3]);
        acc[4]  = fmaf(a1.x, vv, acc[4]);  acc[5]  = fmaf(a1.y, vv, acc[5]);
        acc[6]  = fmaf(a1.z, vv, acc[6]);  acc[7]  = fmaf(a1.w, vv, acc[7]);
        acc[8]  = fmaf(a2.x, vv, acc[8]);  acc[9]  = fmaf(a2.y, vv, acc[9]);
        acc[10] = fmaf(a2.z, vv, acc[10]); acc[11] = fmaf(a2.w, vv, acc[11]);
    }
#pragma unroll
    for (int s = 0; s < KK; s++)
        upd[((size_t)(b * KK + s)) * DD + d] = acc[s] / mass[b * KK + s];
}

// ---------------- tiny multi-head self-attention over the 12 slots ----------------
// qkv: [B, K, 3D]; per (b,h): sc = q.k^T * 96^-0.5, softmax, o = a.v -> obuf [B,K,D]
__global__ void blockattn_kernel(const float* __restrict__ qkv, float* __restrict__ obuf) {
    __shared__ float qs[KK][HD], ks[KK][HD], vs[KK][HD];
    __shared__ float sc[KK][KK], at[KK][KK];
    int b = blockIdx.x, h = blockIdx.y;
    int tid = threadIdx.x;     // 144 threads
    for (int idx = tid; idx < KK * HD; idx += 144) {
        int r = idx / HD, c = idx % HD;
        size_t base = ((size_t)(b * KK + r)) * (3 * DD) + h * HD + c;
        qs[r][c] = qkv[base];
        ks[r][c] = qkv[base + DD];
        vs[r][c] = qkv[base + 2 * DD];
    }
    __syncthreads();
    int i = tid / KK, j = tid % KK;
    {
        float s = 0.f;
#pragma unroll
        for (int d = 0; d < HD; d++) s = fmaf(qs[i][d], ks[j][d], s);
        sc[i][j] = s * SCALE_HD;
    }
    __syncthreads();
    {
        float mx = -1e30f;
#pragma unroll
        for (int jj = 0; jj < KK; jj++) mx = fmaxf(mx, sc[i][jj]);
        float tot = 0.f;
#pragma unroll
        for (int jj = 0; jj < KK; jj++) tot += expf(sc[i][jj] - mx);
        at[i][j] = expf(sc[i][j] - mx) / tot;
    }
    __syncthreads();
    for (int idx = tid; idx < KK * HD; idx += 144) {
        int r = idx / HD, d = idx % HD;
        float s = 0.f;
#pragma unroll
        for (int jj = 0; jj < KK; jj++) s = fmaf(at[r][jj], vs[jj][d], s);
        obuf[((size_t)(b * KK + r)) * DD + h * HD + d] = s;
    }
}

// ---------------- host orchestration ----------------
static float* symaddr(const void* sym) {
    void* p = nullptr;
    cudaGetSymbolAddress(&p, sym);
    return (float*)p;
}

extern "C" void kernel_launch(void* const* d_in, const int* in_sizes, int n_in,
                              void* d_out, int out_size) {
    const float* features  = (const float*)d_in[0];
    const float* slots_init= (const float*)d_in[1];
    const float* nf_g = (const float*)d_in[2];
    const float* nf_b = (const float*)d_in[3];
    const float* ns_g = (const float*)d_in[4];
    const float* ns_b = (const float*)d_in[5];
    const float* Wq   = (const float*)d_in[6];
    const float* Wk   = (const float*)d_in[7];
    const float* Wv   = (const float*)d_in[8];
    const float* mg   = (const float*)d_in[9];
    const float* mb   = (const float*)d_in[10];
    const float* mW1  = (const float*)d_in[11];
    const float* mb1  = (const float*)d_in[12];
    const float* mW2  = (const float*)d_in[13];
    const float* mb2  = (const float*)d_in[14];
    const float* b_ln1g = (const float*)d_in[15];
    const float* b_ln1b = (const float*)d_in[16];
    const float* b_Wqkv = (const float*)d_in[17];
    const float* b_bqkv = (const float*)d_in[18];
    const float* b_Wo   = (const float*)d_in[19];
    const float* b_bo   = (const float*)d_in[20];
    const float* b_ln2g = (const float*)d_in[21];
    const float* b_ln2b = (const float*)d_in[22];
    const float* b_W1   = (const float*)d_in[23];
    const float* b_b1   = (const float*)d_in[24];
    const float* b_W2   = (const float*)d_in[25];
    const float* b_b2   = (const float*)d_in[26];

    float* fn   = symaddr(g_fn);
    float* kmat = symaddr(g_kmat);
    float* vmat = symaddr(g_vmat);
    float* attn = symaddr(g_attn);
    float* sn   = symaddr(g_sn);
    float* qb   = symaddr(g_q);
    float* mass = symaddr(g_mass);
    float* upd  = symaddr(g_upd);
    float* h1   = symaddr(g_h1);
    float* qkv  = symaddr(g_qkv);
    float* ob   = symaddr(g_o);
    float* x1   = symaddr(g_x1);
    float* h2   = symaddr(g_h2);
    float* g1   = symaddr(g_g1);
    float* x2   = symaddr(g_x2);
    float* h3   = symaddr(g_h3);
    float* g2   = symaddr(g_g2);
    float* slots= symaddr(g_slots);

    auto gemm = [](const float* A, const float* W, const float* bias, const float* add,
                   float* C, int M, int Nc, int Kc, int act) {
        dim3 grid(Nc / 64, (M + 63) / 64);
        gemm_kernel<<<grid, 256>>>(A, W, bias, add, C, M, Nc, Kc, act);
    };

    // one-time: fn = LN(features); kmat = fn@Wk; vmat = fn@Wv
    ln_kernel<<<BNROWS, 256>>>(features, nullptr, nf_g, nf_b, fn);
    gemm(fn, Wk, nullptr, nullptr, kmat, BNROWS, DD, DD, 0);
    gemm(fn, Wv, nullptr, nullptr, vmat, BNROWS, DD, DD, 0);
    cudaMemcpyAsync(slots, slots_init, (size_t)SROWS * DD * sizeof(float),
                    cudaMemcpyDeviceToDevice);

    dim3 qkgrid(BB, (NN + 7) / 8);

    for (int t = 0; t < TT; t++) {
        // slot->feature attention
        ln_kernel<<<SROWS, 256>>>(slots, nullptr, ns_g, ns_b, sn);
        gemm(sn, Wq, nullptr, nullptr, qb, SROWS, DD, DD, 0);
        qk_softmax_kernel<<<qkgrid, 256>>>(qb, kmat, attn);
        mass_kernel<<<BB, 256>>>(attn, mass);
        updates_kernel<<<dim3(BB, DD / 128), 128>>>(attn, vmat, mass, upd);

        // transformer block on x = sn
        const float* ln1g = b_ln1g + (size_t)t * DD;
        const float* ln1b = b_ln1b + (size_t)t * DD;
        const float* Wqkv = b_Wqkv + (size_t)t * DD * 3 * DD;
        const float* bqkv = b_bqkv + (size_t)t * 3 * DD;
        const float* Wo   = b_Wo   + (size_t)t * DD * DD;
        const float* bo   = b_bo   + (size_t)t * DD;
        const float* ln2g = b_ln2g + (size_t)t * DD;
        const float* ln2b = b_ln2b + (size_t)t * DD;
        const float* W1   = b_W1   + (size_t)t * DD * 4 * DD;
        const float* b1   = b_b1   + (size_t)t * 4 * DD;
        const float* W2   = b_W2   + (size_t)t * 4 * DD * DD;
        const float* b2   = b_b2   + (size_t)t * DD;

        ln_kernel<<<SROWS, 256>>>(sn, nullptr, ln1g, ln1b, h1);
        gemm(h1, Wqkv, bqkv, nullptr, qkv, SROWS, 3 * DD, DD, 0);
        blockattn_kernel<<<dim3(BB, HH), 144>>>(qkv, ob);
        gemm(ob, Wo, bo, sn, x1, SROWS, DD, DD, 0);                 // x1 = sn + o@Wo + bo
        ln_kernel<<<SROWS, 256>>>(x1, nullptr, ln2g, ln2b, h2);
        gemm(h2, W1, b1, nullptr, g1, SROWS, 4 * DD, DD, 1);        // gelu
        gemm(g1, W2, b2, x1, x2, SROWS, DD, 4 * DD, 0);             // slots_residual

        // mixer: slots += gelu(LN(upd + x2)@mW1 + mb1)@mW2 + mb2
        ln_kernel<<<SROWS, 256>>>(upd, x2, mg, mb, h3);
        gemm(h3, mW1, mb1, nullptr, g2, SROWS, 4 * DD, DD, 1);      // gelu
        gemm(g2, mW2, mb2, slots, slots, SROWS, DD, 4 * DD, 0);     // slots update (in-place add)
    }

    // final attention -> masks written straight into d_out tail
    float* out_slots = (float*)d_out;
    float* out_masks = out_slots + (size_t)SROWS * DD;
    ln_kernel<<<SROWS, 256>>>(slots, nullptr, ns_g, ns_b, sn);
    gemm(sn, Wq, nullptr, nullptr, qb, SROWS, DD, DD, 0);
    qk_softmax_kernel<<<qkgrid, 256>>>(qb, kmat, out_masks);
    cudaMemcpyAsync(out_slots, slots, (size_t)SROWS * DD * sizeof(float),
                    cudaMemcpyDeviceToDevice);
}

// round 3
// speedup vs baseline: 1.9568x; 1.9568x over previous
#include <cuda_runtime.h>
#include <cuda_bf16.h>
#include <math.h>
#include <stdint.h>

// ---------------- problem constants ----------------
#define BB 32
#define NN 1369
#define DD 768
#define KK 12
#define TT 3
#define HH 8
#define HD 96
#define BNROWS (BB * NN)          // 43808
#define SROWS  (BB * KK)          // 384
#define SCALE_QK 0.03608439182435161f   // 768^-0.5
#define SCALE_HD 0.10206207261596575f   // 96^-0.5

// ---------------- scratch (device globals, no allocation) ----------------
__device__ float g_fn  [(size_t)BNROWS * DD];
__device__ float g_kmat[(size_t)BNROWS * DD];
__device__ float g_vmat[(size_t)BNROWS * DD];
__device__ float g_attn[(size_t)BNROWS * KK];
__device__ float g_sn  [(size_t)SROWS * DD];
__device__ float g_q   [(size_t)SROWS * DD];
__device__ float g_mass[SROWS];
__device__ float g_upd [(size_t)SROWS * DD];
__device__ float g_h1  [(size_t)SROWS * DD];
__device__ float g_qkv [(size_t)SROWS * 3 * DD];
__device__ float g_o   [(size_t)SROWS * DD];
__device__ float g_x1  [(size_t)SROWS * DD];
__device__ float g_h2  [(size_t)SROWS * DD];
__device__ float g_g1  [(size_t)SROWS * 4 * DD];
__device__ float g_x2  [(size_t)SROWS * DD];
__device__ float g_h3  [(size_t)SROWS * DD];
__device__ float g_g2  [(size_t)SROWS * 4 * DD];
__device__ float g_slots[(size_t)SROWS * DD];

// ---------------- helpers ----------------
__device__ __forceinline__ float gelu_exact(float x) {
    return 0.5f * x * (1.0f + erff(x * 0.70710678118654752f));
}

__device__ __forceinline__ uint32_t f2tf(float x) {
    uint32_t y;
    asm("cvt.rna.tf32.f32 %0, %1;" : "=r"(y) : "f"(x));
    return y;
}

__device__ __forceinline__ void cp16(void* smem_dst, const void* gmem_src, bool pred) {
    uint32_t s = (uint32_t)__cvta_generic_to_shared(smem_dst);
    int sz = pred ? 16 : 0;
    asm volatile("cp.async.ca.shared.global [%0], [%1], 16, %2;\n"
                 :: "r"(s), "l"(gmem_src), "r"(sz));
}
__device__ __forceinline__ void cp_commit() { asm volatile("cp.async.commit_group;\n"); }
__device__ __forceinline__ void cp_wait1()  { asm volatile("cp.async.wait_group 1;\n"); }

// ---------------- LayerNorm: out = LN(x [+ x2]) * g + b ; row length 768 ----------------
__global__ void ln_kernel(const float* __restrict__ x, const float* __restrict__ x2,
                          const float* __restrict__ gam, const float* __restrict__ bet,
                          float* __restrict__ out) {
    int r = blockIdx.x;
    int tid = threadIdx.x;
    const float* xr = x + (size_t)r * DD;
    const float* x2r = x2 ? (x2 + (size_t)r * DD) : nullptr;
    float v[3];
    float s = 0.f;
#pragma unroll
    for (int i = 0; i < 3; i++) {
        int d = tid + i * 256;
        float t = xr[d];
        if (x2r) t += x2r[d];
        v[i] = t;
        s += t;
    }
    __shared__ float red[256];
    red[tid] = s;
    __syncthreads();
    for (int off = 128; off > 0; off >>= 1) {
        if (tid < off) red[tid] += red[tid + off];
        __syncthreads();
    }
    float mean = red[0] * (1.0f / DD);
    __syncthreads();
    float s2 = 0.f;
#pragma unroll
    for (int i = 0; i < 3; i++) { float dl = v[i] - mean; s2 += dl * dl; }
    red[tid] = s2;
    __syncthreads();
    for (int off = 128; off > 0; off >>= 1) {
        if (tid < off) red[tid] += red[tid + off];
        __syncthreads();
    }
    float inv = rsqrtf(red[0] * (1.0f / DD) + 1e-5f);
#pragma unroll
    for (int i = 0; i < 3; i++) {
        int d = tid + i * 256;
        out[(size_t)r * DD + d] = (v[i] - mean) * inv * gam[d] + bet[d];
    }
}

// ---------------- TF32 tensor-core GEMM: C = act(A@W + bias) + add ----------------
// A:[M,Kc] row-major fp32, W:[Kc,Nc] row-major fp32, C:[M,Nc] fp32.
// Requires Nc % 128 == 0, Kc % 16 == 0.
// Block tile 128x128, BK=16, 8 warps (warp tile 32x64), double-buffered cp.async.
#define GBM 128
#define GBN 128
#define GBK 16
#define A_STRIDE 20   // 16 + 4 pad (floats)
#define B_STRIDE 136  // 128 + 8 pad (floats)

__global__ __launch_bounds__(256)
void gemm_tc(const float* __restrict__ A, const float* __restrict__ W,
             const float* __restrict__ bias, const float* __restrict__ addsrc,
             float* __restrict__ C, int M, int Nc, int Kc, int act) {
    __shared__ float As[2][GBM * A_STRIDE];   // 2 * 10240 B
    __shared__ float Bs[2][GBK * B_STRIDE];   // 2 * 8704 B

    int tid = threadIdx.x;
    int lane = tid & 31;
    int warp = tid >> 5;
    int warp_m = warp & 3;         // 0..3 -> 32-row slices
    int warp_n = warp >> 2;        // 0..1 -> 64-col slices
    int bm = blockIdx.y * GBM;
    int bn = blockIdx.x * GBN;

    int g  = lane >> 2;            // groupID
    int tg = lane & 3;             // threadID_in_group

    float acc[2][8][4];
#pragma unroll
    for (int i = 0; i < 2; i++)
#pragma unroll
        for (int j = 0; j < 8; j++)
#pragma unroll
            for (int k = 0; k < 4; k++) acc[i][j][k] = 0.f;

    int ntiles = Kc / GBK;

    // ---- prefetch stage 0 ----
    {
        int k0 = 0;
#pragma unroll
        for (int i = 0; i < 2; i++) {
            int id = tid + i * 256;          // 0..511
            int row = id >> 2, c4 = id & 3;  // A: 128 rows x 4 chunks
            bool ok = (bm + row) < M;
            cp16(&As[0][row * A_STRIDE + c4 * 4],
                 A + (size_t)(bm + row) * Kc + k0 + c4 * 4, ok);
        }
#pragma unroll
        for (int i = 0; i < 2; i++) {
            int id = tid + i * 256;
            int row = id >> 5, c4 = id & 31; // B: 16 rows x 32 chunks
            cp16(&Bs[0][row * B_STRIDE + c4 * 4],
                 W + (size_t)(k0 + row) * Nc + bn + c4 * 4, true);
        }
        cp_commit();
    }

    for (int t = 0; t < ntiles; t++) {
        if (t + 1 < ntiles) {
            int k0 = (t + 1) * GBK;
            int buf = (t + 1) & 1;
#pragma unroll
            for (int i = 0; i < 2; i++) {
                int id = tid + i * 256;
                int row = id >> 2, c4 = id & 3;
                bool ok = (bm + row) < M;
                cp16(&As[buf][row * A_STRIDE + c4 * 4],
                     A + (size_t)(bm + row) * Kc + k0 + c4 * 4, ok);
            }
#pragma unroll
            for (int i = 0; i < 2; i++) {
                int id = tid + i * 256;
                int row = id >> 5, c4 = id & 31;
                cp16(&Bs[buf][row * B_STRIDE + c4 * 4],
                     W + (size_t)(k0 + row) * Nc + bn + c4 * 4, true);
            }
        }
        cp_commit();
        cp_wait1();
        __syncthreads();

        int buf = t & 1;
        const float* as = As[buf];
        const float* bs = Bs[buf];
#pragma unroll
        for (int ks = 0; ks < 2; ks++) {
            int k0 = ks * 8;
            uint32_t af[2][4];
#pragma unroll
            for (int tm = 0; tm < 2; tm++) {
                int rb = warp_m * 32 + tm * 16;
                af[tm][0] = f2tf(as[(rb + g)     * A_STRIDE + k0 + tg]);
                af[tm][1] = f2tf(as[(rb + g + 8) * A_STRIDE + k0 + tg]);
                af[tm][2] = f2tf(as[(rb + g)     * A_STRIDE + k0 + tg + 4]);
                af[tm][3] = f2tf(as[(rb + g + 8) * A_STRIDE + k0 + tg + 4]);
            }
            uint32_t bf[8][2];
#pragma unroll
            for (int tn = 0; tn < 8; tn++) {
                int cb = warp_n * 64 + tn * 8;
                bf[tn][0] = f2tf(bs[(k0 + tg)     * B_STRIDE + cb + g]);
                bf[tn][1] = f2tf(bs[(k0 + tg + 4) * B_STRIDE + cb + g]);
            }
#pragma unroll
            for (int tm = 0; tm < 2; tm++)
#pragma unroll
                for (int tn = 0; tn < 8; tn++) {
                    asm volatile(
                        "mma.sync.aligned.m16n8k8.row.col.f32.tf32.tf32.f32 "
                        "{%0,%1,%2,%3}, {%4,%5,%6,%7}, {%8,%9}, {%0,%1,%2,%3};\n"
                        : "+f"(acc[tm][tn][0]), "+f"(acc[tm][tn][1]),
                          "+f"(acc[tm][tn][2]), "+f"(acc[tm][tn][3])
                        : "r"(af[tm][0]), "r"(af[tm][1]), "r"(af[tm][2]), "r"(af[tm][3]),
                          "r"(bf[tn][0]), "r"(bf[tn][1]));
                }
        }
        __syncthreads();
    }

    // ---- epilogue ----
#pragma unroll
    for (int tm = 0; tm < 2; tm++) {
        int r0 = bm + warp_m * 32 + tm * 16 + g;
        int r1 = r0 + 8;
#pragma unroll
        for (int tn = 0; tn < 8; tn++) {
            int c0 = bn + warp_n * 64 + tn * 8 + tg * 2;
#pragma unroll
            for (int half = 0; half < 2; half++) {
                int rr = half ? r1 : r0;
                if (rr >= M) continue;
                float v0 = acc[tm][tn][half * 2 + 0];
                float v1 = acc[tm][tn][half * 2 + 1];
                if (bias) { v0 += bias[c0]; v1 += bias[c0 + 1]; }
                if (act)  { v0 = gelu_exact(v0); v1 = gelu_exact(v1); }
                if (addsrc) {
                    v0 += addsrc[(size_t)rr * Nc + c0];
                    v1 += addsrc[(size_t)rr * Nc + c0 + 1];
                }
                C[(size_t)rr * Nc + c0]     = v0;
                C[(size_t)rr * Nc + c0 + 1] = v1;
            }
        }
    }
}

// ---------------- slot<-feature logits + competitive softmax over K ----------------
__global__ void qk_softmax_kernel(const float* __restrict__ q, const float* __restrict__ kmat,
                                  float* __restrict__ attn) {
    __shared__ float qs[KK][DD];   // 36 KB
    int b = blockIdx.x;
    int tid = threadIdx.x;
    const float* qb = q + (size_t)b * KK * DD;
    for (int i = tid; i < KK * DD; i += 256) qs[i / DD][i % DD] = qb[i];
    __syncthreads();
    int w = tid >> 5, lane = tid & 31;
    int n = blockIdx.y * 8 + w;
    if (n >= NN) return;
    const float* kr = kmat + ((size_t)b * NN + n) * DD;
    float p[KK];
#pragma unroll
    for (int s = 0; s < KK; s++) p[s] = 0.f;
    for (int d = lane; d < DD; d += 32) {
        float kv = kr[d];
#pragma unroll
        for (int s = 0; s < KK; s++) p[s] = fmaf(kv, qs[s][d], p[s]);
    }
#pragma unroll
    for (int s = 0; s < KK; s++)
        for (int off = 16; off; off >>= 1) p[s] += __shfl_xor_sync(0xffffffffu, p[s], off);
    float mx = -1e30f;
#pragma unroll
    for (int s = 0; s < KK; s++) { p[s] *= SCALE_QK; mx = fmaxf(mx, p[s]); }
    float tot = 0.f;
    float e[KK];
#pragma unroll
    for (int s = 0; s < KK; s++) { e[s] = expf(p[s] - mx); tot += e[s]; }
    float invt = 1.0f / tot;
    if (lane < KK) attn[((size_t)b * NN + n) * KK + lane] = e[lane] * invt;
}

// ---------------- mass[b,k] = max(sum_n attn[b,n,k], 1e-8) ----------------
__global__ void mass_kernel(const float* __restrict__ attn, float* __restrict__ mass) {
    int b = blockIdx.x, tid = threadIdx.x;
    float acc[KK];
#pragma unroll
    for (int s = 0; s < KK; s++) acc[s] = 0.f;
    for (int n = tid; n < NN; n += 256) {
        const float4* ar = (const float4*)(attn + ((size_t)b * NN + n) * KK);
        float4 a0 = ar[0], a1 = ar[1], a2 = ar[2];
        acc[0] += a0.x; acc[1] += a0.y; acc[2]  += a0.z; acc[3]  += a0.w;
        acc[4] += a1.x; acc[5] += a1.y; acc[6]  += a1.z; acc[7]  += a1.w;
        acc[8] += a2.x; acc[9] += a2.y; acc[10] += a2.z; acc[11] += a2.w;
    }
    __shared__ float red[KK][257];
#pragma unroll
    for (int s = 0; s < KK; s++) red[s][tid] = acc[s];
    __syncthreads();
    for (int off = 128; off > 0; off >>= 1) {
        if (tid < off)
#pragma unroll
            for (int s = 0; s < KK; s++) red[s][tid] += red[s][tid + off];
        __syncthreads();
    }
    if (tid < KK) mass[b * KK + tid] = fmaxf(red[tid][0], 1e-8f);
}

// ---------------- updates[b,k,d] = (sum_n attn[b,n,k]*v[b,n,d]) / mass[b,k] ----------------
__global__ void updates_kernel(const float* __restrict__ attn, const float* __restrict__ v,
                               const float* __restrict__ mass, float* __restrict__ upd) {
    int b = blockIdx.x;
    int d = blockIdx.y * 128 + threadIdx.x;
    const float* vb = v + (size_t)b * NN * DD;
    const float* ab = attn + (size_t)b * NN * KK;
    float acc[KK];
#pragma unroll
    for (int s = 0; s < KK; s++) acc[s] = 0.f;
    for (int n = 0; n < NN; n++) {
        float vv = vb[(size_t)n * DD + d];
        const float4* ar = (const float4*)(ab + (size_t)n * KK);
        float4 a0 = ar[0], a1 = ar[1], a2 = ar[2];
        acc[0]  = fmaf(a0.x, vv, acc[0]);  acc[1]  = fmaf(a0.y, vv, acc[1]);
        acc[2]  = fmaf(a0.z, vv, acc[2]);  acc[3]  = fmaf(a0.w, vv, acc[3]);
        acc[4]  = fmaf(a1.x, vv, acc[4]);  acc[5]  = fmaf(a1.y, vv, acc[5]);
        acc[6]  = fmaf(a1.z, vv, acc[6]);  acc[7]  = fmaf(a1.w, vv, acc[7]);
        acc[8]  = fmaf(a2.x, vv, acc[8]);  acc[9]  = fmaf(a2.y, vv, acc[9]);
        acc[10] = fmaf(a2.z, vv, acc[10]); acc[11] = fmaf(a2.w, vv, acc[11]);
    }
#pragma unroll
    for (int s = 0; s < KK; s++)
        upd[((size_t)(b * KK + s)) * DD + d] = acc[s] / mass[b * KK + s];
}

// ---------------- tiny multi-head self-attention over the 12 slots ----------------
__global__ void blockattn_kernel(const float* __restrict__ qkv, float* __restrict__ obuf) {
    __shared__ float qs[KK][HD], ks[KK][HD], vs[KK][HD];
    __shared__ float sc[KK][KK], at[KK][KK];
    int b = blockIdx.x, h = blockIdx.y;
    int tid = threadIdx.x;     // 144 threads
    for (int idx = tid; idx < KK * HD; idx += 144) {
        int r = idx / HD, c = idx % HD;
        size_t base = ((size_t)(b * KK + r)) * (3 * DD) + h * HD + c;
        qs[r][c] = qkv[base];
        ks[r][c] = qkv[base + DD];
        vs[r][c] = qkv[base + 2 * DD];
    }
    __syncthreads();
    int i = tid / KK, j = tid % KK;
    {
        float s = 0.f;
#pragma unroll
        for (int d = 0; d < HD; d++) s = fmaf(qs[i][d], ks[j][d], s);
        sc[i][j] = s * SCALE_HD;
    }
    __syncthreads();
    {
        float mx = -1e30f;
#pragma unroll
        for (int jj = 0; jj < KK; jj++) mx = fmaxf(mx, sc[i][jj]);
        float tot = 0.f;
#pragma unroll
        for (int jj = 0; jj < KK; jj++) tot += expf(sc[i][jj] - mx);
        at[i][j] = expf(sc[i][j] - mx) / tot;
    }
    __syncthreads();
    for (int idx = tid; idx < KK * HD; idx += 144) {
        int r = idx / HD, d = idx % HD;
        float s = 0.f;
#pragma unroll
        for (int jj = 0; jj < KK; jj++) s = fmaf(at[r][jj], vs[jj][d], s);
        obuf[((size_t)(b * KK + r)) * DD + h * HD + d] = s;
    }
}

// ---------------- host orchestration ----------------
static float* symaddr(const void* sym) {
    void* p = nullptr;
    cudaGetSymbolAddress(&p, sym);
    return (float*)p;
}

extern "C" void kernel_launch(void* const* d_in, const int* in_sizes, int n_in,
                              void* d_out, int out_size) {
    const float* features  = (const float*)d_in[0];
    const float* slots_init= (const float*)d_in[1];
    const float* nf_g = (const float*)d_in[2];
    const float* nf_b = (const float*)d_in[3];
    const float* ns_g = (const float*)d_in[4];
    const float* ns_b = (const float*)d_in[5];
    const float* Wq   = (const float*)d_in[6];
    const float* Wk   = (const float*)d_in[7];
    const float* Wv   = (const float*)d_in[8];
    const float* mg   = (const float*)d_in[9];
    const float* mb   = (const float*)d_in[10];
    const float* mW1  = (const float*)d_in[11];
    const float* mb1  = (const float*)d_in[12];
    const float* mW2  = (const float*)d_in[13];
    const float* mb2  = (const float*)d_in[14];
    const float* b_ln1g = (const float*)d_in[15];
    const float* b_ln1b = (const float*)d_in[16];
    const float* b_Wqkv = (const float*)d_in[17];
    const float* b_bqkv = (const float*)d_in[18];
    const float* b_Wo   = (const float*)d_in[19];
    const float* b_bo   = (const float*)d_in[20];
    const float* b_ln2g = (const float*)d_in[21];
    const float* b_ln2b = (const float*)d_in[22];
    const float* b_W1   = (const float*)d_in[23];
    const float* b_b1   = (const float*)d_in[24];
    const float* b_W2   = (const float*)d_in[25];
    const float* b_b2   = (const float*)d_in[26];

    float* fn   = symaddr(g_fn);
    float* kmat = symaddr(g_kmat);
    float* vmat = symaddr(g_vmat);
    float* attn = symaddr(g_attn);
    float* sn   = symaddr(g_sn);
    float* qb   = symaddr(g_q);
    float* mass = symaddr(g_mass);
    float* upd  = symaddr(g_upd);
    float* h1   = symaddr(g_h1);
    float* qkv  = symaddr(g_qkv);
    float* ob   = symaddr(g_o);
    float* x1   = symaddr(g_x1);
    float* h2   = symaddr(g_h2);
    float* g1   = symaddr(g_g1);
    float* x2   = symaddr(g_x2);
    float* h3   = symaddr(g_h3);
    float* g2   = symaddr(g_g2);
    float* slots= symaddr(g_slots);

    auto gemm = [](const float* A, const float* W, const float* bias, const float* add,
                   float* C, int M, int Nc, int Kc, int act) {
        dim3 grid(Nc / 128, (M + 127) / 128);
        gemm_tc<<<grid, 256>>>(A, W, bias, add, C, M, Nc, Kc, act);
    };

    // one-time: fn = LN(features); kmat = fn@Wk; vmat = fn@Wv
    ln_kernel<<<BNROWS, 256>>>(features, nullptr, nf_g, nf_b, fn);
    gemm(fn, Wk, nullptr, nullptr, kmat, BNROWS, DD, DD, 0);
    gemm(fn, Wv, nullptr, nullptr, vmat, BNROWS, DD, DD, 0);
    cudaMemcpyAsync(slots, slots_init, (size_t)SROWS * DD * sizeof(float),
                    cudaMemcpyDeviceToDevice);

    dim3 qkgrid(BB, (NN + 7) / 8);

    for (int t = 0; t < TT; t++) {
        // slot->feature attention
        ln_kernel<<<SROWS, 256>>>(slots, nullptr, ns_g, ns_b, sn);
        gemm(sn, Wq, nullptr, nullptr, qb, SROWS, DD, DD, 0);
        qk_softmax_kernel<<<qkgrid, 256>>>(qb, kmat, attn);
        mass_kernel<<<BB, 256>>>(attn, mass);
        updates_kernel<<<dim3(BB, DD / 128), 128>>>(attn, vmat, mass, upd);

        // transformer block on x = sn
        const float* ln1g = b_ln1g + (size_t)t * DD;
        const float* ln1b = b_ln1b + (size_t)t * DD;
        const float* Wqkv = b_Wqkv + (size_t)t * DD * 3 * DD;
        const float* bqkv = b_bqkv + (size_t)t * 3 * DD;
        const float* Wo   = b_Wo   + (size_t)t * DD * DD;
        const float* bo   = b_bo   + (size_t)t * DD;
        const float* ln2g = b_ln2g + (size_t)t * DD;
        const float* ln2b = b_ln2b + (size_t)t * DD;
        const float* W1   = b_W1   + (size_t)t * DD * 4 * DD;
        const float* b1   = b_b1   + (size_t)t * 4 * DD;
        const float* W2   = b_W2   + (size_t)t * 4 * DD * DD;
        const float* b2   = b_b2   + (size_t)t * DD;

        ln_kernel<<<SROWS, 256>>>(sn, nullptr, ln1g, ln1b, h1);
        gemm(h1, Wqkv, bqkv, nullptr, qkv, SROWS, 3 * DD, DD, 0);
        blockattn_kernel<<<dim3(BB, HH), 144>>>(qkv, ob);
        gemm(ob, Wo, bo, sn, x1, SROWS, DD, DD, 0);                 // x1 = sn + o@Wo + bo
        ln_kernel<<<SROWS, 256>>>(x1, nullptr, ln2g, ln2b, h2);
        gemm(h2, W1, b1, nullptr, g1, SROWS, 4 * DD, DD, 1);        // gelu
        gemm(g1, W2, b2, x1, x2, SROWS, DD, 4 * DD, 0);             // slots_residual

        // mixer: slots += gelu(LN(upd + x2)@mW1 + mb1)@mW2 + mb2
        ln_kernel<<<SROWS, 256>>>(upd, x2, mg, mb, h3);
        gemm(h3, mW1, mb1, nullptr, g2, SROWS, 4 * DD, DD, 1);      // gelu
        gemm(g2, mW2, mb2, slots, slots, SROWS, DD, 4 * DD, 0);     // slots update (in-place add)
    }

    // final attention -> masks written straight into d_out tail
    float* out_slots = (float*)d_out;
    float* out_masks = out_slots + (size_t)SROWS * DD;
    ln_kernel<<<SROWS, 256>>>(slots, nullptr, ns_g, ns_b, sn);
    gemm(sn, Wq, nullptr, nullptr, qb, SROWS, DD, DD, 0);
    qk_softmax_kernel<<<qkgrid, 256>>>(qb, kmat, out_masks);
    cudaMemcpyAsync(out_slots, slots, (size_t)SROWS * DD * sizeof(float),
                    cudaMemcpyDeviceToDevice);
}

// round 5
// speedup vs baseline: 2.1997x; 1.1241x over previous
#include <cuda_runtime.h>
#include <cuda_bf16.h>
#include <math.h>
#include <stdint.h>

// ---------------- problem constants ----------------
#define BB 32
#define NN 1369
#define DD 768
#define KK 12
#define TT 3
#define HH 8
#define HD 96
#define BNROWS (BB * NN)          // 43808
#define SROWS  (BB * KK)          // 384
#define SCALE_QK 0.03608439182435161f   // 768^-0.5
#define SCALE_HD 0.10206207261596575f   // 96^-0.5

// weight scratch offsets (floats)
#define W_SZ   589824      // 768*768
#define QKV_SZ 1769472     // 768*2304
#define MLP_SZ 2359296     // 768*3072
#define O_WQ    0
#define O_WK    (O_WQ + W_SZ)
#define O_WV    (O_WK + W_SZ)
#define O_MW1   (O_WV + W_SZ)
#define O_MW2   (O_MW1 + MLP_SZ)
#define O_BQKV  (O_MW2 + MLP_SZ)
#define O_BWO   (O_BQKV + 3 * QKV_SZ)
#define O_BW1   (O_BWO + 3 * W_SZ)
#define O_BW2   (O_BW1 + 3 * MLP_SZ)
#define WTF_TOTAL (O_BW2 + 3 * MLP_SZ)   // 27721728 floats

// ---------------- scratch (device globals, no allocation) ----------------
__device__ float g_wtf [(size_t)WTF_TOTAL];
__device__ float g_fn  [(size_t)BNROWS * DD];
__device__ float g_kmat[(size_t)BNROWS * DD];
__device__ float g_vmat[(size_t)BNROWS * DD];
__device__ float g_attn[(size_t)BNROWS * KK];
__device__ float g_sn  [(size_t)SROWS * DD];
__device__ float g_q   [(size_t)SROWS * DD];
__device__ float g_mass[SROWS];
__device__ float g_upd [(size_t)SROWS * DD];
__device__ float g_h1  [(size_t)SROWS * DD];
__device__ float g_qkv [(size_t)SROWS * 3 * DD];
__device__ float g_o   [(size_t)SROWS * DD];
__device__ float g_x1  [(size_t)SROWS * DD];
__device__ float g_h2  [(size_t)SROWS * DD];
__device__ float g_g1  [(size_t)SROWS * 4 * DD];
__device__ float g_x2  [(size_t)SROWS * DD];
__device__ float g_h3  [(size_t)SROWS * DD];
__device__ float g_g2  [(size_t)SROWS * 4 * DD];
__device__ float g_slots[(size_t)SROWS * DD];

// ---------------- helpers ----------------
__device__ __forceinline__ float gelu_exact(float x) {
    return 0.5f * x * (1.0f + erff(x * 0.70710678118654752f));
}

__device__ __forceinline__ uint32_t f2tf(float x) {
    uint32_t y;
    asm("cvt.rna.tf32.f32 %0, %1;" : "=r"(y) : "f"(x));
    return y;
}

__device__ __forceinline__ void cp16(void* smem_dst, const void* gmem_src, bool pred) {
    uint32_t s = (uint32_t)__cvta_generic_to_shared(smem_dst);
    int sz = pred ? 16 : 0;
    asm volatile("cp.async.ca.shared.global [%0], [%1], 16, %2;\n"
                 :: "r"(s), "l"(gmem_src), "r"(sz));
}
__device__ __forceinline__ void cp_commit() { asm volatile("cp.async.commit_group;\n"); }
__device__ __forceinline__ void cp_wait1()  { asm volatile("cp.async.wait_group 1;\n"); }

// ---------------- weight pre-round to tf32 ----------------
__global__ void round_tf32_kernel(const float4* __restrict__ in, float4* __restrict__ out, int n4) {
    int i = blockIdx.x * 256 + threadIdx.x;
    if (i < n4) {
        float4 v = in[i];
        v.x = __uint_as_float(f2tf(v.x));
        v.y = __uint_as_float(f2tf(v.y));
        v.z = __uint_as_float(f2tf(v.z));
        v.w = __uint_as_float(f2tf(v.w));
        out[i] = v;
    }
}

// ---------------- LayerNorm: out = LN(x [+ x2]) * g + b ; row length 768 ----------------
__global__ void ln_kernel(const float* __restrict__ x, const float* __restrict__ x2,
                          const float* __restrict__ gam, const float* __restrict__ bet,
                          float* __restrict__ out) {
    int r = blockIdx.x;
    int tid = threadIdx.x;
    const float* xr = x + (size_t)r * DD;
    const float* x2r = x2 ? (x2 + (size_t)r * DD) : nullptr;
    float v[3];
    float s = 0.f;
#pragma unroll
    for (int i = 0; i < 3; i++) {
        int d = tid + i * 256;
        float t = xr[d];
        if (x2r) t += x2r[d];
        v[i] = t;
        s += t;
    }
    __shared__ float red[256];
    red[tid] = s;
    __syncthreads();
    for (int off = 128; off > 0; off >>= 1) {
        if (tid < off) red[tid] += red[tid + off];
        __syncthreads();
    }
    float mean = red[0] * (1.0f / DD);
    __syncthreads();
    float s2 = 0.f;
#pragma unroll
    for (int i = 0; i < 3; i++) { float dl = v[i] - mean; s2 += dl * dl; }
    red[tid] = s2;
    __syncthreads();
    for (int off = 128; off > 0; off >>= 1) {
        if (tid < off) red[tid] += red[tid + off];
        __syncthreads();
    }
    float inv = rsqrtf(red[0] * (1.0f / DD) + 1e-5f);
#pragma unroll
    for (int i = 0; i < 3; i++) {
        int d = tid + i * 256;
        out[(size_t)r * DD + d] = (v[i] - mean) * inv * gam[d] + bet[d];
    }
}

// ---------------- TF32 TC GEMM (big, 128x128, BK=16, 8 warps) ----------------
// W must be pre-rounded to tf32. A converted at fragment load.
#define GBM 128
#define GBN 128
#define GBK 16
#define A_STRIDE 20
#define B_STRIDE 136

__global__ __launch_bounds__(256)
void gemm_tc(const float* __restrict__ A, const float* __restrict__ W,
             const float* __restrict__ bias, const float* __restrict__ addsrc,
             float* __restrict__ C, int M, int Nc, int Kc, int act) {
    __shared__ float As[2][GBM * A_STRIDE];
    __shared__ float Bs[2][GBK * B_STRIDE];

    int tid = threadIdx.x;
    int lane = tid & 31;
    int warp = tid >> 5;
    int warp_m = warp & 3;
    int warp_n = warp >> 2;
    int bm = blockIdx.y * GBM;
    int bn = blockIdx.x * GBN;
    int g  = lane >> 2;
    int tg = lane & 3;

    float acc[2][8][4];
#pragma unroll
    for (int i = 0; i < 2; i++)
#pragma unroll
        for (int j = 0; j < 8; j++)
#pragma unroll
            for (int k = 0; k < 4; k++) acc[i][j][k] = 0.f;

    int ntiles = Kc / GBK;
    {
#pragma unroll
        for (int i = 0; i < 2; i++) {
            int id = tid + i * 256;
            int row = id >> 2, c4 = id & 3;
            bool ok = (bm + row) < M;
            cp16(&As[0][row * A_STRIDE + c4 * 4],
                 A + (size_t)(bm + row) * Kc + c4 * 4, ok);
        }
#pragma unroll
        for (int i = 0; i < 2; i++) {
            int id = tid + i * 256;
            int row = id >> 5, c4 = id & 31;
            cp16(&Bs[0][row * B_STRIDE + c4 * 4],
                 W + (size_t)row * Nc + bn + c4 * 4, true);
        }
        cp_commit();
    }

    for (int t = 0; t < ntiles; t++) {
        if (t + 1 < ntiles) {
            int k0 = (t + 1) * GBK;
            int buf = (t + 1) & 1;
#pragma unroll
            for (int i = 0; i < 2; i++) {
                int id = tid + i * 256;
                int row = id >> 2, c4 = id & 3;
                bool ok = (bm + row) < M;
                cp16(&As[buf][row * A_STRIDE + c4 * 4],
                     A + (size_t)(bm + row) * Kc + k0 + c4 * 4, ok);
            }
#pragma unroll
            for (int i = 0; i < 2; i++) {
                int id = tid + i * 256;
                int row = id >> 5, c4 = id & 31;
                cp16(&Bs[buf][row * B_STRIDE + c4 * 4],
                     W + (size_t)(k0 + row) * Nc + bn + c4 * 4, true);
            }
        }
        cp_commit();
        cp_wait1();
        __syncthreads();

        int buf = t & 1;
        const float* as = As[buf];
        const float* bs = Bs[buf];
#pragma unroll
        for (int ks = 0; ks < 2; ks++) {
            int k0 = ks * 8;
            uint32_t af[2][4];
#pragma unroll
            for (int tm = 0; tm < 2; tm++) {
                int rb = warp_m * 32 + tm * 16;
                af[tm][0] = f2tf(as[(rb + g)     * A_STRIDE + k0 + tg]);
                af[tm][1] = f2tf(as[(rb + g + 8) * A_STRIDE + k0 + tg]);
                af[tm][2] = f2tf(as[(rb + g)     * A_STRIDE + k0 + tg + 4]);
                af[tm][3] = f2tf(as[(rb + g + 8) * A_STRIDE + k0 + tg + 4]);
            }
            uint32_t bf[8][2];
#pragma unroll
            for (int tn = 0; tn < 8; tn++) {
                int cb = warp_n * 64 + tn * 8;
                bf[tn][0] = __float_as_uint(bs[(k0 + tg)     * B_STRIDE + cb + g]);
                bf[tn][1] = __float_as_uint(bs[(k0 + tg + 4) * B_STRIDE + cb + g]);
            }
#pragma unroll
            for (int tm = 0; tm < 2; tm++)
#pragma unroll
                for (int tn = 0; tn < 8; tn++) {
                    asm volatile(
                        "mma.sync.aligned.m16n8k8.row.col.f32.tf32.tf32.f32 "
                        "{%0,%1,%2,%3}, {%4,%5,%6,%7}, {%8,%9}, {%0,%1,%2,%3};\n"
                        : "+f"(acc[tm][tn][0]), "+f"(acc[tm][tn][1]),
                          "+f"(acc[tm][tn][2]), "+f"(acc[tm][tn][3])
                        : "r"(af[tm][0]), "r"(af[tm][1]), "r"(af[tm][2]), "r"(af[tm][3]),
                          "r"(bf[tn][0]), "r"(bf[tn][1]));
                }
        }
        __syncthreads();
    }

#pragma unroll
    for (int tm = 0; tm < 2; tm++) {
        int r0 = bm + warp_m * 32 + tm * 16 + g;
        int r1 = r0 + 8;
#pragma unroll
        for (int tn = 0; tn < 8; tn++) {
            int c0 = bn + warp_n * 64 + tn * 8 + tg * 2;
#pragma unroll
            for (int half = 0; half < 2; half++) {
                int rr = half ? r1 : r0;
                if (rr >= M) continue;
                float v0 = acc[tm][tn][half * 2 + 0];
                float v1 = acc[tm][tn][half * 2 + 1];
                if (bias) { v0 += bias[c0]; v1 += bias[c0 + 1]; }
                if (act)  { v0 = gelu_exact(v0); v1 = gelu_exact(v1); }
                if (addsrc) {
                    v0 += addsrc[(size_t)rr * Nc + c0];
                    v1 += addsrc[(size_t)rr * Nc + c0 + 1];
                }
                C[(size_t)rr * Nc + c0]     = v0;
                C[(size_t)rr * Nc + c0 + 1] = v1;
            }
        }
    }
}

// ---------------- TF32 TC GEMM (small-M, 64x64, BK=32, 4 warps) ----------------
#define SBM 64
#define SBN 64
#define SBK 32
#define SA_STR 36   // 32 + 4 pad
#define SB_STR 72   // 64 + 8 pad

__global__ __launch_bounds__(128)
void gemm_tc64(const float* __restrict__ A, const float* __restrict__ W,
               const float* __restrict__ bias, const float* __restrict__ addsrc,
               float* __restrict__ C, int M, int Nc, int Kc, int act) {
    __shared__ float As[2][SBM * SA_STR];
    __shared__ float Bs[2][SBK * SB_STR];

    int tid = threadIdx.x;
    int lane = tid & 31;
    int warp = tid >> 5;          // 0..3
    int warp_m = warp & 1;        // 32-row slice
    int warp_n = warp >> 1;       // 32-col slice
    int bm = blockIdx.y * SBM;
    int bn = blockIdx.x * SBN;
    int g  = lane >> 2;
    int tg = lane & 3;

    float acc[2][4][4];
#pragma unroll
    for (int i = 0; i < 2; i++)
#pragma unroll
        for (int j = 0; j < 4; j++)
#pragma unroll
            for (int k = 0; k < 4; k++) acc[i][j][k] = 0.f;

    int ntiles = Kc / SBK;
    {
#pragma unroll
        for (int i = 0; i < 4; i++) {
            int id = tid + i * 128;          // 0..511; A: 64 rows x 8 f4-chunks
            int row = id >> 3, c4 = id & 7;
            bool ok = (bm + row) < M;
            cp16(&As[0][row * SA_STR + c4 * 4],
                 A + (size_t)(bm + row) * Kc + c4 * 4, ok);
        }
#pragma unroll
        for (int i = 0; i < 4; i++) {
            int id = tid + i * 128;          // B: 32 rows x 16 chunks
            int row = id >> 4, c4 = id & 15;
            cp16(&Bs[0][row * SB_STR + c4 * 4],
                 W + (size_t)row * Nc + bn + c4 * 4, true);
        }
        cp_commit();
    }

    for (int t = 0; t < ntiles; t++) {
        if (t + 1 < ntiles) {
            int k0 = (t + 1) * SBK;
            int buf = (t + 1) & 1;
#pragma unroll
            for (int i = 0; i < 4; i++) {
                int id = tid + i * 128;
                int row = id >> 3, c4 = id & 7;
                bool ok = (bm + row) < M;
                cp16(&As[buf][row * SA_STR + c4 * 4],
                     A + (size_t)(bm + row) * Kc + k0 + c4 * 4, ok);
            }
#pragma unroll
            for (int i = 0; i < 4; i++) {
                int id = tid + i * 128;
                int row = id >> 4, c4 = id & 15;
                cp16(&Bs[buf][row * SB_STR + c4 * 4],
                     W + (size_t)(k0 + row) * Nc + bn + c4 * 4, true);
            }
        }
        cp_commit();
        cp_wait1();
        __syncthreads();

        int buf = t & 1;
        const float* as = As[buf];
        const float* bs = Bs[buf];
#pragma unroll
        for (int ks = 0; ks < 4; ks++) {
            int k0 = ks * 8;
            uint32_t af[2][4];
#pragma unroll
            for (int tm = 0; tm < 2; tm++) {
                int rb = warp_m * 32 + tm * 16;
                af[tm][0] = f2tf(as[(rb + g)     * SA_STR + k0 + tg]);
                af[tm][1] = f2tf(as[(rb + g + 8) * SA_STR + k0 + tg]);
                af[tm][2] = f2tf(as[(rb + g)     * SA_STR + k0 + tg + 4]);
                af[tm][3] = f2tf(as[(rb + g + 8) * SA_STR + k0 + tg + 4]);
            }
            uint32_t bf[4][2];
#pragma unroll
            for (int tn = 0; tn < 4; tn++) {
                int cb = warp_n * 32 + tn * 8;
                bf[tn][0] = __float_as_uint(bs[(k0 + tg)     * SB_STR + cb + g]);
                bf[tn][1] = __float_as_uint(bs[(k0 + tg + 4) * SB_STR + cb + g]);
            }
#pragma unroll
            for (int tm = 0; tm < 2; tm++)
#pragma unroll
                for (int tn = 0; tn < 4; tn++) {
                    asm volatile(
                        "mma.sync.aligned.m16n8k8.row.col.f32.tf32.tf32.f32 "
                        "{%0,%1,%2,%3}, {%4,%5,%6,%7}, {%8,%9}, {%0,%1,%2,%3};\n"
                        : "+f"(acc[tm][tn][0]), "+f"(acc[tm][tn][1]),
                          "+f"(acc[tm][tn][2]), "+f"(acc[tm][tn][3])
                        : "r"(af[tm][0]), "r"(af[tm][1]), "r"(af[tm][2]), "r"(af[tm][3]),
                          "r"(bf[tn][0]), "r"(bf[tn][1]));
                }
        }
        __syncthreads();
    }

#pragma unroll
    for (int tm = 0; tm < 2; tm++) {
        int r0 = bm + warp_m * 32 + tm * 16 + g;
        int r1 = r0 + 8;
#pragma unroll
        for (int tn = 0; tn < 4; tn++) {
            int c0 = bn + warp_n * 32 + tn * 8 + tg * 2;
#pragma unroll
            for (int half = 0; half < 2; half++) {
                int rr = half ? r1 : r0;
                if (rr >= M) continue;
                float v0 = acc[tm][tn][half * 2 + 0];
                float v1 = acc[tm][tn][half * 2 + 1];
                if (bias) { v0 += bias[c0]; v1 += bias[c0 + 1]; }
                if (act)  { v0 = gelu_exact(v0); v1 = gelu_exact(v1); }
                if (addsrc) {
                    v0 += addsrc[(size_t)rr * Nc + c0];
                    v1 += addsrc[(size_t)rr * Nc + c0 + 1];
                }
                C[(size_t)rr * Nc + c0]     = v0;
                C[(size_t)rr * Nc + c0 + 1] = v1;
            }
        }
    }
}

// ---------------- slot<-feature logits + competitive softmax over K ----------------
// 512 threads, 16 tokens per block, float4 loads everywhere.
__global__ __launch_bounds__(512)
void qk_softmax_kernel(const float* __restrict__ q, const float* __restrict__ kmat,
                       float* __restrict__ attn) {
    __shared__ float qs[KK][DD];   // 36 KB, rows contiguous
    int b = blockIdx.x;
    int tid = threadIdx.x;
    const float4* qb4 = (const float4*)(q + (size_t)b * KK * DD);
    float4* qs4 = (float4*)&qs[0][0];
    for (int i = tid; i < KK * DD / 4; i += 512) qs4[i] = qb4[i];
    __syncthreads();
    int w = tid >> 5, lane = tid & 31;
    int n = blockIdx.y * 16 + w;
    if (n >= NN) return;
    const float4* kr4 = (const float4*)(kmat + ((size_t)b * NN + n) * DD);
    float p[KK];
#pragma unroll
    for (int s = 0; s < KK; s++) p[s] = 0.f;
#pragma unroll
    for (int it = 0; it < 6; it++) {
        int d4 = it * 32 + lane;
        float4 kv = kr4[d4];
#pragma unroll
        for (int s = 0; s < KK; s++) {
            const float4 qv = ((const float4*)qs[s])[d4];
            p[s] = fmaf(kv.x, qv.x, p[s]);
            p[s] = fmaf(kv.y, qv.y, p[s]);
            p[s] = fmaf(kv.z, qv.z, p[s]);
            p[s] = fmaf(kv.w, qv.w, p[s]);
        }
    }
#pragma unroll
    for (int s = 0; s < KK; s++)
        for (int off = 16; off; off >>= 1) p[s] += __shfl_xor_sync(0xffffffffu, p[s], off);
    float mx = -1e30f;
#pragma unroll
    for (int s = 0; s < KK; s++) { p[s] *= SCALE_QK; mx = fmaxf(mx, p[s]); }
    float tot = 0.f;
    float e[KK];
#pragma unroll
    for (int s = 0; s < KK; s++) { e[s] = expf(p[s] - mx); tot += e[s]; }
    float invt = 1.0f / tot;
    if (lane < KK) attn[((size_t)b * NN + n) * KK + lane] = e[lane] * invt;
}

// ---------------- mass[b,k] = max(sum_n attn[b,n,k], 1e-8) ----------------
__global__ void mass_kernel(const float* __restrict__ attn, float* __restrict__ mass) {
    int b = blockIdx.x, tid = threadIdx.x;
    float acc[KK];
#pragma unroll
    for (int s = 0; s < KK; s++) acc[s] = 0.f;
    for (int n = tid; n < NN; n += 256) {
        const float4* ar = (const float4*)(attn + ((size_t)b * NN + n) * KK);
        float4 a0 = ar[0], a1 = ar[1], a2 = ar[2];
        acc[0] += a0.x; acc[1] += a0.y; acc[2]  += a0.z; acc[3]  += a0.w;
        acc[4] += a1.x; acc[5] += a1.y; acc[6]  += a1.z; acc[7]  += a1.w;
        acc[8] += a2.x; acc[9] += a2.y; acc[10] += a2.z; acc[11] += a2.w;
    }
    __shared__ float red[KK][257];
#pragma unroll
    for (int s = 0; s < KK; s++) red[s][tid] = acc[s];
    __syncthreads();
    for (int off = 128; off > 0; off >>= 1) {
        if (tid < off)
#pragma unroll
            for (int s = 0; s < KK; s++) red[s][tid] += red[s][tid + off];
        __syncthreads();
    }
    if (tid < KK) mass[b * KK + tid] = fmaxf(red[tid][0], 1e-8f);
}

// ---------------- updates[b,k,d] = (sum_n attn[b,n,k]*v[b,n,d]) / mass[b,k] ----------------
__global__ void updates_kernel(const float* __restrict__ attn, const float* __restrict__ v,
                               const float* __restrict__ mass, float* __restrict__ upd) {
    int b = blockIdx.x;
    int d = blockIdx.y * 128 + threadIdx.x;
    const float* vb = v + (size_t)b * NN * DD;
    const float* ab = attn + (size_t)b * NN * KK;
    float acc[KK];
#pragma unroll
    for (int s = 0; s < KK; s++) acc[s] = 0.f;
#pragma unroll 4
    for (int n = 0; n < NN; n++) {
        float vv = __ldg(vb + (size_t)n * DD + d);
        const float4* ar = (const float4*)(ab + (size_t)n * KK);
        float4 a0 = __ldg(ar), a1 = __ldg(ar + 1), a2 = __ldg(ar + 2);
        acc[0]  = fmaf(a0.x, vv, acc[0]);  acc[1]  = fmaf(a0.y, vv, acc[1]);
        acc[2]  = fmaf(a0.z, vv, acc[2]);  acc[3]  = fmaf(a0.w, vv, acc[3]);
        acc[4]  = fmaf(a1.x, vv, acc[4]);  acc[5]  = fmaf(a1.y, vv, acc[5]);
        acc[6]  = fmaf(a1.z, vv, acc[6]);  acc[7]  = fmaf(a1.w, vv, acc[7]);
        acc[8]  = fmaf(a2.x, vv, acc[8]);  acc[9]  = fmaf(a2.y, vv, acc[9]);
        acc[10] = fmaf(a2.z, vv, acc[10]); acc[11] = fmaf(a2.w, vv, acc[11]);
    }
#pragma unroll
    for (int s = 0; s < KK; s++)
        upd[((size_t)(b * KK + s)) * DD + d] = acc[s] / mass[b * KK + s];
}

// ---------------- tiny multi-head self-attention over the 12 slots ----------------
__global__ void blockattn_kernel(const float* __restrict__ qkv, float* __restrict__ obuf) {
    __shared__ float qs[KK][HD], ks[KK][HD], vs[KK][HD];
    __shared__ float sc[KK][KK], at[KK][KK];
    int b = blockIdx.x, h = blockIdx.y;
    int tid = threadIdx.x;     // 144 threads
    for (int idx = tid; idx < KK * HD; idx += 144) {
        int r = idx / HD, c = idx % HD;
        size_t base = ((size_t)(b * KK + r)) * (3 * DD) + h * HD + c;
        qs[r][c] = qkv[base];
        ks[r][c] = qkv[base + DD];
        vs[r][c] = qkv[base + 2 * DD];
    }
    __syncthreads();
    int i = tid / KK, j = tid % KK;
    {
        float s = 0.f;
#pragma unroll
        for (int d = 0; d < HD; d++) s = fmaf(qs[i][d], ks[j][d], s);
        sc[i][j] = s * SCALE_HD;
    }
    __syncthreads();
    {
        float mx = -1e30f;
#pragma unroll
        for (int jj = 0; jj < KK; jj++) mx = fmaxf(mx, sc[i][jj]);
        float tot = 0.f;
#pragma unroll
        for (int jj = 0; jj < KK; jj++) tot += expf(sc[i][jj] - mx);
        at[i][j] = expf(sc[i][j] - mx) / tot;
    }
    __syncthreads();
    for (int idx = tid; idx < KK * HD; idx += 144) {
        int r = idx / HD, d = idx % HD;
        float s = 0.f;
#pragma unroll
        for (int jj = 0; jj < KK; jj++) s = fmaf(at[r][jj], vs[jj][d], s);
        obuf[((size_t)(b * KK + r)) * DD + h * HD + d] = s;
    }
}

// ---------------- host orchestration ----------------
static float* symaddr(const void* sym) {
    void* p = nullptr;
    cudaGetSymbolAddress(&p, sym);
    return (float*)p;
}

extern "C" void kernel_launch(void* const* d_in, const int* in_sizes, int n_in,
                              void* d_out, int out_size) {
    const float* features  = (const float*)d_in[0];
    const float* slots_init= (const float*)d_in[1];
    const float* nf_g = (const float*)d_in[2];
    const float* nf_b = (const float*)d_in[3];
    const float* ns_g = (const float*)d_in[4];
    const float* ns_b = (const float*)d_in[5];
    const float* Wq   = (const float*)d_in[6];
    const float* Wk   = (const float*)d_in[7];
    const float* Wv   = (const float*)d_in[8];
    const float* mg   = (const float*)d_in[9];
    const float* mb   = (const float*)d_in[10];
    const float* mW1  = (const float*)d_in[11];
    const float* mb1  = (const float*)d_in[12];
    const float* mW2  = (const float*)d_in[13];
    const float* mb2  = (const float*)d_in[14];
    const float* b_ln1g = (const float*)d_in[15];
    const float* b_ln1b = (const float*)d_in[16];
    const float* b_Wqkv = (const float*)d_in[17];
    const float* b_bqkv = (const float*)d_in[18];
    const float* b_Wo   = (const float*)d_in[19];
    const float* b_bo   = (const float*)d_in[20];
    const float* b_ln2g = (const float*)d_in[21];
    const float* b_ln2b = (const float*)d_in[22];
    const float* b_W1   = (const float*)d_in[23];
    const float* b_b1   = (const float*)d_in[24];
    const float* b_W2   = (const float*)d_in[25];
    const float* b_b2   = (const float*)d_in[26];

    float* wtf  = symaddr(g_wtf);
    float* fn   = symaddr(g_fn);
    float* kmat = symaddr(g_kmat);
    float* vmat = symaddr(g_vmat);
    float* attn = symaddr(g_attn);
    float* sn   = symaddr(g_sn);
    float* qb   = symaddr(g_q);
    float* mass = symaddr(g_mass);
    float* upd  = symaddr(g_upd);
    float* h1   = symaddr(g_h1);
    float* qkv  = symaddr(g_qkv);
    float* ob   = symaddr(g_o);
    float* x1   = symaddr(g_x1);
    float* h2   = symaddr(g_h2);
    float* g1   = symaddr(g_g1);
    float* x2   = symaddr(g_x2);
    float* h3   = symaddr(g_h3);
    float* g2   = symaddr(g_g2);
    float* slots= symaddr(g_slots);

    auto roundw = [&](const float* src, float* dst, int n) {
        int n4 = n / 4;
        round_tf32_kernel<<<(n4 + 255) / 256, 256>>>((const float4*)src, (float4*)dst, n4);
    };
    // pre-round all GEMM B operands into wtf
    roundw(Wq,    wtf + O_WQ,   W_SZ);
    roundw(Wk,    wtf + O_WK,   W_SZ);
    roundw(Wv,    wtf + O_WV,   W_SZ);
    roundw(mW1,   wtf + O_MW1,  MLP_SZ);
    roundw(mW2,   wtf + O_MW2,  MLP_SZ);
    roundw(b_Wqkv, wtf + O_BQKV, 3 * QKV_SZ);
    roundw(b_Wo,   wtf + O_BWO,  3 * W_SZ);
    roundw(b_W1,   wtf + O_BW1,  3 * MLP_SZ);
    roundw(b_W2,   wtf + O_BW2,  3 * MLP_SZ);

    auto gemm = [](const float* A, const float* W, const float* bias, const float* add,
                   float* C, int M, int Nc, int Kc, int act) {
        dim3 grid(Nc / 128, (M + 127) / 128);
        gemm_tc<<<grid, 256>>>(A, W, bias, add, C, M, Nc, Kc, act);
    };
    auto gemmS = [](const float* A, const float* W, const float* bias, const float* add,
                    float* C, int Nc, int Kc, int act) {
        dim3 grid(Nc / 64, SROWS / 64);
        gemm_tc64<<<grid, 128>>>(A, W, bias, add, C, SROWS, Nc, Kc, act);
    };

    // one-time: fn = LN(features); kmat = fn@Wk; vmat = fn@Wv
    ln_kernel<<<BNROWS, 256>>>(features, nullptr, nf_g, nf_b, fn);
    gemm(fn, wtf + O_WK, nullptr, nullptr, kmat, BNROWS, DD, DD, 0);
    gemm(fn, wtf + O_WV, nullptr, nullptr, vmat, BNROWS, DD, DD, 0);
    cudaMemcpyAsync(slots, slots_init, (size_t)SROWS * DD * sizeof(float),
                    cudaMemcpyDeviceToDevice);

    dim3 qkgrid(BB, (NN + 15) / 16);

    for (int t = 0; t < TT; t++) {
        // slot->feature attention
        ln_kernel<<<SROWS, 256>>>(slots, nullptr, ns_g, ns_b, sn);
        gemmS(sn, wtf + O_WQ, nullptr, nullptr, qb, DD, DD, 0);
        qk_softmax_kernel<<<qkgrid, 512>>>(qb, kmat, attn);
        mass_kernel<<<BB, 256>>>(attn, mass);
        updates_kernel<<<dim3(BB, DD / 128), 128>>>(attn, vmat, mass, upd);

        // transformer block on x = sn
        const float* ln1g = b_ln1g + (size_t)t * DD;
        const float* ln1b = b_ln1b + (size_t)t * DD;
        const float* Wqkvt = wtf + O_BQKV + (size_t)t * QKV_SZ;
        const float* bqkv = b_bqkv + (size_t)t * 3 * DD;
        const float* Wot  = wtf + O_BWO + (size_t)t * W_SZ;
        const float* bo   = b_bo   + (size_t)t * DD;
        const float* ln2g = b_ln2g + (size_t)t * DD;
        const float* ln2b = b_ln2b + (size_t)t * DD;
        const float* W1t  = wtf + O_BW1 + (size_t)t * MLP_SZ;
        const float* b1   = b_b1   + (size_t)t * 4 * DD;
        const float* W2t  = wtf + O_BW2 + (size_t)t * MLP_SZ;
        const float* b2   = b_b2   + (size_t)t * DD;

        ln_kernel<<<SROWS, 256>>>(sn, nullptr, ln1g, ln1b, h1);
        gemmS(h1, Wqkvt, bqkv, nullptr, qkv, 3 * DD, DD, 0);
        blockattn_kernel<<<dim3(BB, HH), 144>>>(qkv, ob);
        gemmS(ob, Wot, bo, sn, x1, DD, DD, 0);                  // x1 = sn + o@Wo + bo
        ln_kernel<<<SROWS, 256>>>(x1, nullptr, ln2g, ln2b, h2);
        gemmS(h2, W1t, b1, nullptr, g1, 4 * DD, DD, 1);         // gelu
        gemmS(g1, W2t, b2, x1, x2, DD, 4 * DD, 0);              // slots_residual

        // mixer: slots += gelu(LN(upd + x2)@mW1 + mb1)@mW2 + mb2
        ln_kernel<<<SROWS, 256>>>(upd, x2, mg, mb, h3);
        gemmS(h3, wtf + O_MW1, mb1, nullptr, g2, 4 * DD, DD, 1);
        gemmS(g2, wtf + O_MW2, mb2, slots, slots, DD, 4 * DD, 0);
    }

    // final attention -> masks written straight into d_out tail
    float* out_slots = (float*)d_out;
    float* out_masks = out_slots + (size_t)SROWS * DD;
    ln_kernel<<<SROWS, 256>>>(slots, nullptr, ns_g, ns_b, sn);
    gemmS(sn, wtf + O_WQ, nullptr, nullptr, qb, DD, DD, 0);
    qk_softmax_kernel<<<qkgrid, 512>>>(qb, kmat, out_masks);
    cudaMemcpyAsync(out_slots, slots, (size_t)SROWS * DD * sizeof(float),
                    cudaMemcpyDeviceToDevice);
}

// round 6
// speedup vs baseline: 2.2173x; 1.0080x over previous
#include <cuda_runtime.h>
#include <cuda_bf16.h>
#include <math.h>
#include <stdint.h>

// ---------------- problem constants ----------------
#define BB 32
#define NN 1369
#define DD 768
#define KK 12
#define TT 3
#define HH 8
#define HD 96
#define BNROWS (BB * NN)          // 43808
#define SROWS  (BB * KK)          // 384
#define KVLD   1536               // fused K|V row stride
#define SCALE_QK 0.03608439182435161f   // 768^-0.5
#define SCALE_HD 0.10206207261596575f   // 96^-0.5

// weight scratch offsets (floats)
#define W_SZ   589824      // 768*768
#define KV_SZ  1179648     // 768*1536
#define QKV_SZ 1769472     // 768*2304
#define MLP_SZ 2359296     // 768*3072
#define O_WQ    0
#define O_WKV   (O_WQ + W_SZ)
#define O_MW1   (O_WKV + KV_SZ)
#define O_MW2   (O_MW1 + MLP_SZ)
#define O_BQKV  (O_MW2 + MLP_SZ)
#define O_BWO   (O_BQKV + 3 * QKV_SZ)
#define O_BW1   (O_BWO + 3 * W_SZ)
#define O_BW2   (O_BW1 + 3 * MLP_SZ)
#define WTF_TOTAL (O_BW2 + 3 * MLP_SZ)

// ---------------- scratch (device globals, no allocation) ----------------
__device__ float g_wtf [(size_t)WTF_TOTAL];
__device__ float g_fn  [(size_t)BNROWS * DD];
__device__ float g_kv  [(size_t)BNROWS * KVLD];   // cols 0..767 = K, 768..1535 = V
__device__ float g_attn[(size_t)BNROWS * KK];
__device__ float g_sn  [(size_t)SROWS * DD];
__device__ float g_q   [(size_t)SROWS * DD];
__device__ float g_mass[SROWS];
__device__ float g_upd [(size_t)SROWS * DD];
__device__ float g_h1  [(size_t)SROWS * DD];
__device__ float g_qkv [(size_t)SROWS * 3 * DD];
__device__ float g_o   [(size_t)SROWS * DD];
__device__ float g_x1  [(size_t)SROWS * DD];
__device__ float g_h2  [(size_t)SROWS * DD];
__device__ float g_g1  [(size_t)SROWS * 4 * DD];
__device__ float g_x2  [(size_t)SROWS * DD];
__device__ float g_h3  [(size_t)SROWS * DD];
__device__ float g_g2  [(size_t)SROWS * 4 * DD];
__device__ float g_slots[(size_t)SROWS * DD];

// ---------------- helpers ----------------
__device__ __forceinline__ float gelu_exact(float x) {
    return 0.5f * x * (1.0f + erff(x * 0.70710678118654752f));
}

__device__ __forceinline__ uint32_t f2tf(float x) {
    uint32_t y;
    asm("cvt.rna.tf32.f32 %0, %1;" : "=r"(y) : "f"(x));
    return y;
}

__device__ __forceinline__ void cp16(void* smem_dst, const void* gmem_src, bool pred) {
    uint32_t s = (uint32_t)__cvta_generic_to_shared(smem_dst);
    int sz = pred ? 16 : 0;
    asm volatile("cp.async.ca.shared.global [%0], [%1], 16, %2;\n"
                 :: "r"(s), "l"(gmem_src), "r"(sz));
}
__device__ __forceinline__ void cp_commit() { asm volatile("cp.async.commit_group;\n"); }
__device__ __forceinline__ void cp_wait1()  { asm volatile("cp.async.wait_group 1;\n"); }

// ---------------- weight pre-round to tf32 ----------------
__global__ void round_tf32_kernel(const float4* __restrict__ in, float4* __restrict__ out, int n4) {
    int i = blockIdx.x * 256 + threadIdx.x;
    if (i < n4) {
        float4 v = in[i];
        v.x = __uint_as_float(f2tf(v.x));
        v.y = __uint_as_float(f2tf(v.y));
        v.z = __uint_as_float(f2tf(v.z));
        v.w = __uint_as_float(f2tf(v.w));
        out[i] = v;
    }
}

// pack Wk|Wv side-by-side into [768, 1536], rounded to tf32
__global__ void pack_kv_kernel(const float4* __restrict__ Wk, const float4* __restrict__ Wv,
                               float4* __restrict__ out) {
    int i = blockIdx.x * 256 + threadIdx.x;       // over 768*1536/4 = 294912
    if (i >= KV_SZ / 4) return;
    int r = i / (KVLD / 4);
    int c4 = i % (KVLD / 4);                      // 0..383
    float4 v = (c4 < DD / 4) ? Wk[r * (DD / 4) + c4]
                             : Wv[r * (DD / 4) + (c4 - DD / 4)];
    v.x = __uint_as_float(f2tf(v.x));
    v.y = __uint_as_float(f2tf(v.y));
    v.z = __uint_as_float(f2tf(v.z));
    v.w = __uint_as_float(f2tf(v.w));
    out[i] = v;
}

// ---------------- LayerNorm: out = LN(x [+ x2]) * g + b ; row length 768 ----------------
// round_out: additionally round the result to tf32 (for GEMM-A-only consumers)
__global__ void ln_kernel(const float* __restrict__ x, const float* __restrict__ x2,
                          const float* __restrict__ gam, const float* __restrict__ bet,
                          float* __restrict__ out, int round_out) {
    int r = blockIdx.x;
    int tid = threadIdx.x;
    const float* xr = x + (size_t)r * DD;
    const float* x2r = x2 ? (x2 + (size_t)r * DD) : nullptr;
    float v[3];
    float s = 0.f;
#pragma unroll
    for (int i = 0; i < 3; i++) {
        int d = tid + i * 256;
        float t = xr[d];
        if (x2r) t += x2r[d];
        v[i] = t;
        s += t;
    }
    __shared__ float red[256];
    red[tid] = s;
    __syncthreads();
    for (int off = 128; off > 0; off >>= 1) {
        if (tid < off) red[tid] += red[tid + off];
        __syncthreads();
    }
    float mean = red[0] * (1.0f / DD);
    __syncthreads();
    float s2 = 0.f;
#pragma unroll
    for (int i = 0; i < 3; i++) { float dl = v[i] - mean; s2 += dl * dl; }
    red[tid] = s2;
    __syncthreads();
    for (int off = 128; off > 0; off >>= 1) {
        if (tid < off) red[tid] += red[tid + off];
        __syncthreads();
    }
    float inv = rsqrtf(red[0] * (1.0f / DD) + 1e-5f);
#pragma unroll
    for (int i = 0; i < 3; i++) {
        int d = tid + i * 256;
        float o = (v[i] - mean) * inv * gam[d] + bet[d];
        if (round_out) o = __uint_as_float(f2tf(o));
        out[(size_t)r * DD + d] = o;
    }
}

// ---------------- TF32 TC GEMM (big, 128x128, BK=16, 8 warps) ----------------
// BOTH A and W must be pre-rounded to tf32 (no cvt in the inner loop).
#define GBM 128
#define GBN 128
#define GBK 16
#define A_STRIDE 20
#define B_STRIDE 136

__global__ __launch_bounds__(256)
void gemm_tc(const float* __restrict__ A, const float* __restrict__ W,
             float* __restrict__ C, int M, int Nc, int Kc) {
    __shared__ float As[2][GBM * A_STRIDE];
    __shared__ float Bs[2][GBK * B_STRIDE];

    int tid = threadIdx.x;
    int lane = tid & 31;
    int warp = tid >> 5;
    int warp_m = warp & 3;
    int warp_n = warp >> 2;
    int bm = blockIdx.y * GBM;
    int bn = blockIdx.x * GBN;
    int g  = lane >> 2;
    int tg = lane & 3;

    float acc[2][8][4];
#pragma unroll
    for (int i = 0; i < 2; i++)
#pragma unroll
        for (int j = 0; j < 8; j++)
#pragma unroll
            for (int k = 0; k < 4; k++) acc[i][j][k] = 0.f;

    int ntiles = Kc / GBK;
    {
#pragma unroll
        for (int i = 0; i < 2; i++) {
            int id = tid + i * 256;
            int row = id >> 2, c4 = id & 3;
            bool ok = (bm + row) < M;
            cp16(&As[0][row * A_STRIDE + c4 * 4],
                 A + (size_t)(bm + row) * Kc + c4 * 4, ok);
        }
#pragma unroll
        for (int i = 0; i < 2; i++) {
            int id = tid + i * 256;
            int row = id >> 5, c4 = id & 31;
            cp16(&Bs[0][row * B_STRIDE + c4 * 4],
                 W + (size_t)row * Nc + bn + c4 * 4, true);
        }
        cp_commit();
    }

    for (int t = 0; t < ntiles; t++) {
        if (t + 1 < ntiles) {
            int k0 = (t + 1) * GBK;
            int buf = (t + 1) & 1;
#pragma unroll
            for (int i = 0; i < 2; i++) {
                int id = tid + i * 256;
                int row = id >> 2, c4 = id & 3;
                bool ok = (bm + row) < M;
                cp16(&As[buf][row * A_STRIDE + c4 * 4],
                     A + (size_t)(bm + row) * Kc + k0 + c4 * 4, ok);
            }
#pragma unroll
            for (int i = 0; i < 2; i++) {
                int id = tid + i * 256;
                int row = id >> 5, c4 = id & 31;
                cp16(&Bs[buf][row * B_STRIDE + c4 * 4],
                     W + (size_t)(k0 + row) * Nc + bn + c4 * 4, true);
            }
        }
        cp_commit();
        cp_wait1();
        __syncthreads();

        int buf = t & 1;
        const float* as = As[buf];
        const float* bs = Bs[buf];
#pragma unroll
        for (int ks = 0; ks < 2; ks++) {
            int k0 = ks * 8;
            uint32_t af[2][4];
#pragma unroll
            for (int tm = 0; tm < 2; tm++) {
                int rb = warp_m * 32 + tm * 16;
                af[tm][0] = __float_as_uint(as[(rb + g)     * A_STRIDE + k0 + tg]);
                af[tm][1] = __float_as_uint(as[(rb + g + 8) * A_STRIDE + k0 + tg]);
                af[tm][2] = __float_as_uint(as[(rb + g)     * A_STRIDE + k0 + tg + 4]);
                af[tm][3] = __float_as_uint(as[(rb + g + 8) * A_STRIDE + k0 + tg + 4]);
            }
            uint32_t bf[8][2];
#pragma unroll
            for (int tn = 0; tn < 8; tn++) {
                int cb = warp_n * 64 + tn * 8;
                bf[tn][0] = __float_as_uint(bs[(k0 + tg)     * B_STRIDE + cb + g]);
                bf[tn][1] = __float_as_uint(bs[(k0 + tg + 4) * B_STRIDE + cb + g]);
            }
#pragma unroll
            for (int tm = 0; tm < 2; tm++)
#pragma unroll
                for (int tn = 0; tn < 8; tn++) {
                    asm volatile(
                        "mma.sync.aligned.m16n8k8.row.col.f32.tf32.tf32.f32 "
                        "{%0,%1,%2,%3}, {%4,%5,%6,%7}, {%8,%9}, {%0,%1,%2,%3};\n"
                        : "+f"(acc[tm][tn][0]), "+f"(acc[tm][tn][1]),
                          "+f"(acc[tm][tn][2]), "+f"(acc[tm][tn][3])
                        : "r"(af[tm][0]), "r"(af[tm][1]), "r"(af[tm][2]), "r"(af[tm][3]),
                          "r"(bf[tn][0]), "r"(bf[tn][1]));
                }
        }
        __syncthreads();
    }

#pragma unroll
    for (int tm = 0; tm < 2; tm++) {
        int r0 = bm + warp_m * 32 + tm * 16 + g;
        int r1 = r0 + 8;
#pragma unroll
        for (int tn = 0; tn < 8; tn++) {
            int c0 = bn + warp_n * 64 + tn * 8 + tg * 2;
#pragma unroll
            for (int half = 0; half < 2; half++) {
                int rr = half ? r1 : r0;
                if (rr >= M) continue;
                C[(size_t)rr * Nc + c0]     = acc[tm][tn][half * 2 + 0];
                C[(size_t)rr * Nc + c0 + 1] = acc[tm][tn][half * 2 + 1];
            }
        }
    }
}

// ---------------- TF32 TC GEMM (small-M, 32x64, BK=32, 4 warps) ----------------
#define TBM 32
#define TBN 64
#define TBK 32
#define TA_STR 36   // 32 + 4 pad
#define TB_STR 72   // 64 + 8 pad

__global__ __launch_bounds__(128)
void gemm_tc32(const float* __restrict__ A, const float* __restrict__ W,
               const float* __restrict__ bias, const float* __restrict__ addsrc,
               float* __restrict__ C, int M, int Nc, int Kc, int act) {
    __shared__ float As[2][TBM * TA_STR];
    __shared__ float Bs[2][TBK * TB_STR];

    int tid = threadIdx.x;
    int lane = tid & 31;
    int warp = tid >> 5;          // 0..3
    int warp_m = warp & 1;        // 16-row slice
    int warp_n = warp >> 1;       // 32-col slice
    int bm = blockIdx.y * TBM;
    int bn = blockIdx.x * TBN;
    int g  = lane >> 2;
    int tg = lane & 3;

    float acc[4][4];
#pragma unroll
    for (int j = 0; j < 4; j++)
#pragma unroll
        for (int k = 0; k < 4; k++) acc[j][k] = 0.f;

    int ntiles = Kc / TBK;
    {
#pragma unroll
        for (int i = 0; i < 2; i++) {
            int id = tid + i * 128;          // A: 32 rows x 8 f4-chunks = 256
            int row = id >> 3, c4 = id & 7;
            bool ok = (bm + row) < M;
            cp16(&As[0][row * TA_STR + c4 * 4],
                 A + (size_t)(bm + row) * Kc + c4 * 4, ok);
        }
#pragma unroll
        for (int i = 0; i < 4; i++) {
            int id = tid + i * 128;          // B: 32 rows x 16 chunks = 512
            int row = id >> 4, c4 = id & 15;
            cp16(&Bs[0][row * TB_STR + c4 * 4],
                 W + (size_t)row * Nc + bn + c4 * 4, true);
        }
        cp_commit();
    }

    for (int t = 0; t < ntiles; t++) {
        if (t + 1 < ntiles) {
            int k0 = (t + 1) * TBK;
            int buf = (t + 1) & 1;
#pragma unroll
            for (int i = 0; i < 2; i++) {
                int id = tid + i * 128;
                int row = id >> 3, c4 = id & 7;
                bool ok = (bm + row) < M;
                cp16(&As[buf][row * TA_STR + c4 * 4],
                     A + (size_t)(bm + row) * Kc + k0 + c4 * 4, ok);
            }
#pragma unroll
            for (int i = 0; i < 4; i++) {
                int id = tid + i * 128;
                int row = id >> 4, c4 = id & 15;
                cp16(&Bs[buf][row * TB_STR + c4 * 4],
                     W + (size_t)(k0 + row) * Nc + bn + c4 * 4, true);
            }
        }
        cp_commit();
        cp_wait1();
        __syncthreads();

        int buf = t & 1;
        const float* as = As[buf];
        const float* bs = Bs[buf];
#pragma unroll
        for (int ks = 0; ks < 4; ks++) {
            int k0 = ks * 8;
            int rb = warp_m * 16;
            uint32_t af[4];
            af[0] = f2tf(as[(rb + g)     * TA_STR + k0 + tg]);
            af[1] = f2tf(as[(rb + g + 8) * TA_STR + k0 + tg]);
            af[2] = f2tf(as[(rb + g)     * TA_STR + k0 + tg + 4]);
            af[3] = f2tf(as[(rb + g + 8) * TA_STR + k0 + tg + 4]);
            uint32_t bf[4][2];
#pragma unroll
            for (int tn = 0; tn < 4; tn++) {
                int cb = warp_n * 32 + tn * 8;
                bf[tn][0] = __float_as_uint(bs[(k0 + tg)     * TB_STR + cb + g]);
                bf[tn][1] = __float_as_uint(bs[(k0 + tg + 4) * TB_STR + cb + g]);
            }
#pragma unroll
            for (int tn = 0; tn < 4; tn++) {
                asm volatile(
                    "mma.sync.aligned.m16n8k8.row.col.f32.tf32.tf32.f32 "
                    "{%0,%1,%2,%3}, {%4,%5,%6,%7}, {%8,%9}, {%0,%1,%2,%3};\n"
                    : "+f"(acc[tn][0]), "+f"(acc[tn][1]),
                      "+f"(acc[tn][2]), "+f"(acc[tn][3])
                    : "r"(af[0]), "r"(af[1]), "r"(af[2]), "r"(af[3]),
                      "r"(bf[tn][0]), "r"(bf[tn][1]));
            }
        }
        __syncthreads();
    }

    {
        int r0 = bm + warp_m * 16 + g;
        int r1 = r0 + 8;
#pragma unroll
        for (int tn = 0; tn < 4; tn++) {
            int c0 = bn + warp_n * 32 + tn * 8 + tg * 2;
#pragma unroll
            for (int half = 0; half < 2; half++) {
                int rr = half ? r1 : r0;
                if (rr >= M) continue;
                float v0 = acc[tn][half * 2 + 0];
                float v1 = acc[tn][half * 2 + 1];
                if (bias) { v0 += bias[c0]; v1 += bias[c0 + 1]; }
                if (act)  { v0 = gelu_exact(v0); v1 = gelu_exact(v1); }
                if (addsrc) {
                    v0 += addsrc[(size_t)rr * Nc + c0];
                    v1 += addsrc[(size_t)rr * Nc + c0 + 1];
                }
                C[(size_t)rr * Nc + c0]     = v0;
                C[(size_t)rr * Nc + c0 + 1] = v1;
            }
        }
    }
}

// ---------------- slot<-feature logits + competitive softmax over K ----------------
__global__ __launch_bounds__(512)
void qk_softmax_kernel(const float* __restrict__ q, const float* __restrict__ kmat,
                       int ldk, float* __restrict__ attn) {
    __shared__ float qs[KK][DD];
    int b = blockIdx.x;
    int tid = threadIdx.x;
    const float4* qb4 = (const float4*)(q + (size_t)b * KK * DD);
    float4* qs4 = (float4*)&qs[0][0];
    for (int i = tid; i < KK * DD / 4; i += 512) qs4[i] = qb4[i];
    __syncthreads();
    int w = tid >> 5, lane = tid & 31;
    int n = blockIdx.y * 16 + w;
    if (n >= NN) return;
    const float4* kr4 = (const float4*)(kmat + ((size_t)b * NN + n) * ldk);
    float p[KK];
#pragma unroll
    for (int s = 0; s < KK; s++) p[s] = 0.f;
#pragma unroll
    for (int it = 0; it < 6; it++) {
        int d4 = it * 32 + lane;
        float4 kv = kr4[d4];
#pragma unroll
        for (int s = 0; s < KK; s++) {
            const float4 qv = ((const float4*)qs[s])[d4];
            p[s] = fmaf(kv.x, qv.x, p[s]);
            p[s] = fmaf(kv.y, qv.y, p[s]);
            p[s] = fmaf(kv.z, qv.z, p[s]);
            p[s] = fmaf(kv.w, qv.w, p[s]);
        }
    }
#pragma unroll
    for (int s = 0; s < KK; s++)
        for (int off = 16; off; off >>= 1) p[s] += __shfl_xor_sync(0xffffffffu, p[s], off);
    float mx = -1e30f;
#pragma unroll
    for (int s = 0; s < KK; s++) { p[s] *= SCALE_QK; mx = fmaxf(mx, p[s]); }
    float tot = 0.f;
    float e[KK];
#pragma unroll
    for (int s = 0; s < KK; s++) { e[s] = expf(p[s] - mx); tot += e[s]; }
    float invt = 1.0f / tot;
    if (lane < KK) attn[((size_t)b * NN + n) * KK + lane] = e[lane] * invt;
}

// ---------------- mass[b,k] = max(sum_n attn[b,n,k], 1e-8) ----------------
__global__ void mass_kernel(const float* __restrict__ attn, float* __restrict__ mass) {
    int b = blockIdx.x, tid = threadIdx.x;
    float acc[KK];
#pragma unroll
    for (int s = 0; s < KK; s++) acc[s] = 0.f;
    for (int n = tid; n < NN; n += 256) {
        const float4* ar = (const float4*)(attn + ((size_t)b * NN + n) * KK);
        float4 a0 = ar[0], a1 = ar[1], a2 = ar[2];
        acc[0] += a0.x; acc[1] += a0.y; acc[2]  += a0.z; acc[3]  += a0.w;
        acc[4] += a1.x; acc[5] += a1.y; acc[6]  += a1.z; acc[7]  += a1.w;
        acc[8] += a2.x; acc[9] += a2.y; acc[10] += a2.z; acc[11] += a2.w;
    }
    __shared__ float red[KK][257];
#pragma unroll
    for (int s = 0; s < KK; s++) red[s][tid] = acc[s];
    __syncthreads();
    for (int off = 128; off > 0; off >>= 1) {
        if (tid < off)
#pragma unroll
            for (int s = 0; s < KK; s++) red[s][tid] += red[s][tid + off];
        __syncthreads();
    }
    if (tid < KK) mass[b * KK + tid] = fmaxf(red[tid][0], 1e-8f);
}

// ---------------- updates[b,k,d] = (sum_n attn[b,n,k]*v[b,n,d]) / mass[b,k] ----------------
__global__ void updates_kernel(const float* __restrict__ attn, const float* __restrict__ v,
                               int ldv, const float* __restrict__ mass, float* __restrict__ upd) {
    int b = blockIdx.x;
    int d = blockIdx.y * 128 + threadIdx.x;
    const float* vb = v + (size_t)b * NN * ldv;
    const float* ab = attn + (size_t)b * NN * KK;
    float acc[KK];
#pragma unroll
    for (int s = 0; s < KK; s++) acc[s] = 0.f;
#pragma unroll 4
    for (int n = 0; n < NN; n++) {
        float vv = __ldg(vb + (size_t)n * ldv + d);
        const float4* ar = (const float4*)(ab + (size_t)n * KK);
        float4 a0 = __ldg(ar), a1 = __ldg(ar + 1), a2 = __ldg(ar + 2);
        acc[0]  = fmaf(a0.x, vv, acc[0]);  acc[1]  = fmaf(a0.y, vv, acc[1]);
        acc[2]  = fmaf(a0.z, vv, acc[2]);  acc[3]  = fmaf(a0.w, vv, acc[3]);
        acc[4]  = fmaf(a1.x, vv, acc[4]);  acc[5]  = fmaf(a1.y, vv, acc[5]);
        acc[6]  = fmaf(a1.z, vv, acc[6]);  acc[7]  = fmaf(a1.w, vv, acc[7]);
        acc[8]  = fmaf(a2.x, vv, acc[8]);  acc[9]  = fmaf(a2.y, vv, acc[9]);
        acc[10] = fmaf(a2.z, vv, acc[10]); acc[11] = fmaf(a2.w, vv, acc[11]);
    }
#pragma unroll
    for (int s = 0; s < KK; s++)
        upd[((size_t)(b * KK + s)) * DD + d] = acc[s] / mass[b * KK + s];
}

// ---------------- tiny multi-head self-attention over the 12 slots ----------------
__global__ void blockattn_kernel(const float* __restrict__ qkv, float* __restrict__ obuf) {
    __shared__ float qs[KK][HD], ks[KK][HD], vs[KK][HD];
    __shared__ float sc[KK][KK], at[KK][KK];
    int b = blockIdx.x, h = blockIdx.y;
    int tid = threadIdx.x;     // 144 threads
    for (int idx = tid; idx < KK * HD; idx += 144) {
        int r = idx / HD, c = idx % HD;
        size_t base = ((size_t)(b * KK + r)) * (3 * DD) + h * HD + c;
        qs[r][c] = qkv[base];
        ks[r][c] = qkv[base + DD];
        vs[r][c] = qkv[base + 2 * DD];
    }
    __syncthreads();
    int i = tid / KK, j = tid % KK;
    {
        float s = 0.f;
#pragma unroll
        for (int d = 0; d < HD; d++) s = fmaf(qs[i][d], ks[j][d], s);
        sc[i][j] = s * SCALE_HD;
    }
    __syncthreads();
    {
        float mx = -1e30f;
#pragma unroll
        for (int jj = 0; jj < KK; jj++) mx = fmaxf(mx, sc[i][jj]);
        float tot = 0.f;
#pragma unroll
        for (int jj = 0; jj < KK; jj++) tot += expf(sc[i][jj] - mx);
        at[i][j] = expf(sc[i][j] - mx) / tot;
    }
    __syncthreads();
    for (int idx = tid; idx < KK * HD; idx += 144) {
        int r = idx / HD, d = idx % HD;
        float s = 0.f;
#pragma unroll
        for (int jj = 0; jj < KK; jj++) s = fmaf(at[r][jj], vs[jj][d], s);
        obuf[((size_t)(b * KK + r)) * DD + h * HD + d] = s;
    }
}

// ---------------- host orchestration ----------------
static float* symaddr(const void* sym) {
    void* p = nullptr;
    cudaGetSymbolAddress(&p, sym);
    return (float*)p;
}

extern "C" void kernel_launch(void* const* d_in, const int* in_sizes, int n_in,
                              void* d_out, int out_size) {
    const float* features  = (const float*)d_in[0];
    const float* slots_init= (const float*)d_in[1];
    const float* nf_g = (const float*)d_in[2];
    const float* nf_b = (const float*)d_in[3];
    const float* ns_g = (const float*)d_in[4];
    const float* ns_b = (const float*)d_in[5];
    const float* Wq   = (const float*)d_in[6];
    const float* Wk   = (const float*)d_in[7];
    const float* Wv   = (const float*)d_in[8];
    const float* mg   = (const float*)d_in[9];
    const float* mb   = (const float*)d_in[10];
    const float* mW1  = (const float*)d_in[11];
    const float* mb1  = (const float*)d_in[12];
    const float* mW2  = (const float*)d_in[13];
    const float* mb2  = (const float*)d_in[14];
    const float* b_ln1g = (const float*)d_in[15];
    const float* b_ln1b = (const float*)d_in[16];
    const float* b_Wqkv = (const float*)d_in[17];
    const float* b_bqkv = (const float*)d_in[18];
    const float* b_Wo   = (const float*)d_in[19];
    const float* b_bo   = (const float*)d_in[20];
    const float* b_ln2g = (const float*)d_in[21];
    const float* b_ln2b = (const float*)d_in[22];
    const float* b_W1   = (const float*)d_in[23];
    const float* b_b1   = (const float*)d_in[24];
    const float* b_W2   = (const float*)d_in[25];
    const float* b_b2   = (const float*)d_in[26];

    float* wtf  = symaddr(g_wtf);
    float* fn   = symaddr(g_fn);
    float* kv   = symaddr(g_kv);
    float* attn = symaddr(g_attn);
    float* sn   = symaddr(g_sn);
    float* qb   = symaddr(g_q);
    float* mass = symaddr(g_mass);
    float* upd  = symaddr(g_upd);
    float* h1   = symaddr(g_h1);
    float* qkv  = symaddr(g_qkv);
    float* ob   = symaddr(g_o);
    float* x1   = symaddr(g_x1);
    float* h2   = symaddr(g_h2);
    float* g1   = symaddr(g_g1);
    float* x2   = symaddr(g_x2);
    float* h3   = symaddr(g_h3);
    float* g2   = symaddr(g_g2);
    float* slots= symaddr(g_slots);

    auto roundw = [&](const float* src, float* dst, int n) {
        int n4 = n / 4;
        round_tf32_kernel<<<(n4 + 255) / 256, 256>>>((const float4*)src, (float4*)dst, n4);
    };
    roundw(Wq,     wtf + O_WQ,   W_SZ);
    pack_kv_kernel<<<(KV_SZ / 4 + 255) / 256, 256>>>((const float4*)Wk, (const float4*)Wv,
                                                     (float4*)(wtf + O_WKV));
    roundw(mW1,    wtf + O_MW1,  MLP_SZ);
    roundw(mW2,    wtf + O_MW2,  MLP_SZ);
    roundw(b_Wqkv, wtf + O_BQKV, 3 * QKV_SZ);
    roundw(b_Wo,   wtf + O_BWO,  3 * W_SZ);
    roundw(b_W1,   wtf + O_BW1,  3 * MLP_SZ);
    roundw(b_W2,   wtf + O_BW2,  3 * MLP_SZ);

    auto gemmS = [](const float* A, const float* W, const float* bias, const float* add,
                    float* C, int Nc, int Kc, int act) {
        dim3 grid(Nc / TBN, SROWS / TBM);
        gemm_tc32<<<grid, 128>>>(A, W, bias, add, C, SROWS, Nc, Kc, act);
    };

    // one-time: fn = tf32(LN(features)); kv = fn@[Wk|Wv]
    ln_kernel<<<BNROWS, 256>>>(features, nullptr, nf_g, nf_b, fn, 1);
    {
        dim3 grid(KVLD / GBN, (BNROWS + GBM - 1) / GBM);
        gemm_tc<<<grid, 256>>>(fn, wtf + O_WKV, kv, BNROWS, KVLD, DD);
    }
    cudaMemcpyAsync(slots, slots_init, (size_t)SROWS * DD * sizeof(float),
                    cudaMemcpyDeviceToDevice);

    dim3 qkgrid(BB, (NN + 15) / 16);

    for (int t = 0; t < TT; t++) {
        // slot->feature attention
        ln_kernel<<<SROWS, 256>>>(slots, nullptr, ns_g, ns_b, sn, 0);
        gemmS(sn, wtf + O_WQ, nullptr, nullptr, qb, DD, DD, 0);
        qk_softmax_kernel<<<qkgrid, 512>>>(qb, kv, KVLD, attn);
        mass_kernel<<<BB, 256>>>(attn, mass);
        updates_kernel<<<dim3(BB, DD / 128), 128>>>(attn, kv + DD, KVLD, mass, upd);

        // transformer block on x = sn
        const float* ln1g = b_ln1g + (size_t)t * DD;
        const float* ln1b = b_ln1b + (size_t)t * DD;
        const float* Wqkvt = wtf + O_BQKV + (size_t)t * QKV_SZ;
        const float* bqkv = b_bqkv + (size_t)t * 3 * DD;
        const float* Wot  = wtf + O_BWO + (size_t)t * W_SZ;
        const float* bo   = b_bo   + (size_t)t * DD;
        const float* ln2g = b_ln2g + (size_t)t * DD;
        const float* ln2b = b_ln2b + (size_t)t * DD;
        const float* W1t  = wtf + O_BW1 + (size_t)t * MLP_SZ;
        const float* b1   = b_b1   + (size_t)t * 4 * DD;
        const float* W2t  = wtf + O_BW2 + (size_t)t * MLP_SZ;
        const float* b2   = b_b2   + (size_t)t * DD;

        ln_kernel<<<SROWS, 256>>>(sn, nullptr, ln1g, ln1b, h1, 0);
        gemmS(h1, Wqkvt, bqkv, nullptr, qkv, 3 * DD, DD, 0);
        blockattn_kernel<<<dim3(BB, HH), 144>>>(qkv, ob);
        gemmS(ob, Wot, bo, sn, x1, DD, DD, 0);                  // x1 = sn + o@Wo + bo
        ln_kernel<<<SROWS, 256>>>(x1, nullptr, ln2g, ln2b, h2, 0);
        gemmS(h2, W1t, b1, nullptr, g1, 4 * DD, DD, 1);         // gelu
        gemmS(g1, W2t, b2, x1, x2, DD, 4 * DD, 0);              // slots_residual

        // mixer: slots += gelu(LN(upd + x2)@mW1 + mb1)@mW2 + mb2
        ln_kernel<<<SROWS, 256>>>(upd, x2, mg, mb, h3, 0);
        gemmS(h3, wtf + O_MW1, mb1, nullptr, g2, 4 * DD, DD, 1);
        gemmS(g2, wtf + O_MW2, mb2, slots, slots, DD, 4 * DD, 0);
    }

    // final attention -> masks written straight into d_out tail
    float* out_slots = (float*)d_out;
    float* out_masks = out_slots + (size_t)SROWS * DD;
    ln_kernel<<<SROWS, 256>>>(slots, nullptr, ns_g, ns_b, sn, 0);
    gemmS(sn, wtf + O_WQ, nullptr, nullptr, qb, DD, DD, 0);
    qk_softmax_kernel<<<qkgrid, 512>>>(qb, kv, KVLD, out_masks);
    cudaMemcpyAsync(out_slots, slots, (size_t)SROWS * DD * sizeof(float),
                    cudaMemcpyDeviceToDevice);
}

// round 7
// speedup vs baseline: 2.8116x; 1.2680x over previous
#include <cuda_runtime.h>
#include <cuda_bf16.h>
#include <math.h>
#include <stdint.h>

// ---------------- problem constants ----------------
#define BB 32
#define NN 1369
#define DD 768
#define KK 12
#define TT 3
#define HH 8
#define HD 96
#define BNROWS (BB * NN)          // 43808
#define SROWS  (BB * KK)          // 384
#define SCALE_QK 0.03608439182435161f   // 768^-0.5
#define SCALE_HD 0.10206207261596575f   // 96^-0.5

// weight scratch offsets (floats)
#define W_SZ   589824      // 768*768
#define QKV_SZ 1769472     // 768*2304
#define MLP_SZ 2359296     // 768*3072
#define O_WKT   0
#define O_WQK   (O_WKT + W_SZ)
#define O_WV    (O_WQK + W_SZ)
#define O_MW1   (O_WV + W_SZ)
#define O_MW2   (O_MW1 + MLP_SZ)
#define O_BQKV  (O_MW2 + MLP_SZ)
#define O_BWO   (O_BQKV + 3 * QKV_SZ)
#define O_BW1   (O_BWO + 3 * W_SZ)
#define O_BW2   (O_BW1 + 3 * MLP_SZ)
#define WTF_TOTAL (O_BW2 + 3 * MLP_SZ)

// ---------------- scratch (device globals, no allocation) ----------------
__device__ float g_wtf [(size_t)WTF_TOTAL];
__device__ float g_fn  [(size_t)BNROWS * DD];
__device__ float g_attn[(size_t)BNROWS * KK];
__device__ float g_sn  [(size_t)SROWS * DD];
__device__ float g_q   [(size_t)SROWS * DD];
__device__ float g_mass[SROWS];
__device__ float g_ub  [(size_t)SROWS * DD];
__device__ float g_upd [(size_t)SROWS * DD];
__device__ float g_h1  [(size_t)SROWS * DD];
__device__ float g_qkv [(size_t)SROWS * 3 * DD];
__device__ float g_o   [(size_t)SROWS * DD];
__device__ float g_x1  [(size_t)SROWS * DD];
__device__ float g_h2  [(size_t)SROWS * DD];
__device__ float g_g1  [(size_t)SROWS * 4 * DD];
__device__ float g_x2  [(size_t)SROWS * DD];
__device__ float g_h3  [(size_t)SROWS * DD];
__device__ float g_g2  [(size_t)SROWS * 4 * DD];
__device__ float g_slots[(size_t)SROWS * DD];

// ---------------- helpers ----------------
__device__ __forceinline__ float gelu_exact(float x) {
    return 0.5f * x * (1.0f + erff(x * 0.70710678118654752f));
}

__device__ __forceinline__ uint32_t f2tf(float x) {
    uint32_t y;
    asm("cvt.rna.tf32.f32 %0, %1;" : "=r"(y) : "f"(x));
    return y;
}

__device__ __forceinline__ void cp16(void* smem_dst, const void* gmem_src, bool pred) {
    uint32_t s = (uint32_t)__cvta_generic_to_shared(smem_dst);
    int sz = pred ? 16 : 0;
    asm volatile("cp.async.ca.shared.global [%0], [%1], 16, %2;\n"
                 :: "r"(s), "l"(gmem_src), "r"(sz));
}
__device__ __forceinline__ void cp_commit() { asm volatile("cp.async.commit_group;\n"); }
__device__ __forceinline__ void cp_wait1()  { asm volatile("cp.async.wait_group 1;\n"); }

// ---------------- weight pre-round to tf32 ----------------
__global__ void round_tf32_kernel(const float4* __restrict__ in, float4* __restrict__ out, int n4) {
    int i = blockIdx.x * 256 + threadIdx.x;
    if (i < n4) {
        float4 v = in[i];
        v.x = __uint_as_float(f2tf(v.x));
        v.y = __uint_as_float(f2tf(v.y));
        v.z = __uint_as_float(f2tf(v.z));
        v.w = __uint_as_float(f2tf(v.w));
        out[i] = v;
    }
}

// transpose 768x768 and round to tf32: out[k][j] = tf32(in[j][k])
__global__ void transpose_round_kernel(const float* __restrict__ in, float* __restrict__ out) {
    __shared__ float tile[32][33];
    int bx = blockIdx.x * 32, by = blockIdx.y * 32;
    int x = bx + threadIdx.x;
#pragma unroll
    for (int dy = 0; dy < 32; dy += 8) {
        int y = by + threadIdx.y + dy;
        tile[threadIdx.y + dy][threadIdx.x] = in[(size_t)y * DD + x];
    }
    __syncthreads();
    int xo = by + threadIdx.x;
#pragma unroll
    for (int dy = 0; dy < 32; dy += 8) {
        int yo = bx + threadIdx.y + dy;
        out[(size_t)yo * DD + xo] = __uint_as_float(f2tf(tile[threadIdx.x][threadIdx.y + dy]));
    }
}

// ---------------- LayerNorm: out = LN(x [+ x2]) * g + b ; row length 768 ----------------
__global__ void ln_kernel(const float* __restrict__ x, const float* __restrict__ x2,
                          const float* __restrict__ gam, const float* __restrict__ bet,
                          float* __restrict__ out) {
    int r = blockIdx.x;
    int tid = threadIdx.x;
    const float* xr = x + (size_t)r * DD;
    const float* x2r = x2 ? (x2 + (size_t)r * DD) : nullptr;
    float v[3];
    float s = 0.f;
#pragma unroll
    for (int i = 0; i < 3; i++) {
        int d = tid + i * 256;
        float t = xr[d];
        if (x2r) t += x2r[d];
        v[i] = t;
        s += t;
    }
    __shared__ float red[256];
    red[tid] = s;
    __syncthreads();
    for (int off = 128; off > 0; off >>= 1) {
        if (tid < off) red[tid] += red[tid + off];
        __syncthreads();
    }
    float mean = red[0] * (1.0f / DD);
    __syncthreads();
    float s2 = 0.f;
#pragma unroll
    for (int i = 0; i < 3; i++) { float dl = v[i] - mean; s2 += dl * dl; }
    red[tid] = s2;
    __syncthreads();
    for (int off = 128; off > 0; off >>= 1) {
        if (tid < off) red[tid] += red[tid + off];
        __syncthreads();
    }
    float inv = rsqrtf(red[0] * (1.0f / DD) + 1e-5f);
#pragma unroll
    for (int i = 0; i < 3; i++) {
        int d = tid + i * 256;
        out[(size_t)r * DD + d] = (v[i] - mean) * inv * gam[d] + bet[d];
    }
}

// ---------------- TF32 TC GEMM (32x64 tiles, BK=32, 4 warps) ----------------
// act: 0=none, 1=gelu, 2=round output to tf32
#define TBM 32
#define TBN 64
#define TBK 32
#define TA_STR 36   // 32 + 4 pad
#define TB_STR 72   // 64 + 8 pad

__global__ __launch_bounds__(128)
void gemm_tc32(const float* __restrict__ A, const float* __restrict__ W,
               const float* __restrict__ bias, const float* __restrict__ addsrc,
               float* __restrict__ C, int M, int Nc, int Kc, int act) {
    __shared__ float As[2][TBM * TA_STR];
    __shared__ float Bs[2][TBK * TB_STR];

    int tid = threadIdx.x;
    int lane = tid & 31;
    int warp = tid >> 5;          // 0..3
    int warp_m = warp & 1;        // 16-row slice
    int warp_n = warp >> 1;       // 32-col slice
    int bm = blockIdx.y * TBM;
    int bn = blockIdx.x * TBN;
    int g  = lane >> 2;
    int tg = lane & 3;

    float acc[4][4];
#pragma unroll
    for (int j = 0; j < 4; j++)
#pragma unroll
        for (int k = 0; k < 4; k++) acc[j][k] = 0.f;

    int ntiles = Kc / TBK;
    {
#pragma unroll
        for (int i = 0; i < 2; i++) {
            int id = tid + i * 128;          // A: 32 rows x 8 f4-chunks
            int row = id >> 3, c4 = id & 7;
            bool ok = (bm + row) < M;
            cp16(&As[0][row * TA_STR + c4 * 4],
                 A + (size_t)(bm + row) * Kc + c4 * 4, ok);
        }
#pragma unroll
        for (int i = 0; i < 4; i++) {
            int id = tid + i * 128;          // B: 32 rows x 16 chunks
            int row = id >> 4, c4 = id & 15;
            cp16(&Bs[0][row * TB_STR + c4 * 4],
                 W + (size_t)row * Nc + bn + c4 * 4, true);
        }
        cp_commit();
    }

    for (int t = 0; t < ntiles; t++) {
        if (t + 1 < ntiles) {
            int k0 = (t + 1) * TBK;
            int buf = (t + 1) & 1;
#pragma unroll
            for (int i = 0; i < 2; i++) {
                int id = tid + i * 128;
                int row = id >> 3, c4 = id & 7;
                bool ok = (bm + row) < M;
                cp16(&As[buf][row * TA_STR + c4 * 4],
                     A + (size_t)(bm + row) * Kc + k0 + c4 * 4, ok);
            }
#pragma unroll
            for (int i = 0; i < 4; i++) {
                int id = tid + i * 128;
                int row = id >> 4, c4 = id & 15;
                cp16(&Bs[buf][row * TB_STR + c4 * 4],
                     W + (size_t)(k0 + row) * Nc + bn + c4 * 4, true);
            }
        }
        cp_commit();
        cp_wait1();
        __syncthreads();

        int buf = t & 1;
        const float* as = As[buf];
        const float* bs = Bs[buf];
#pragma unroll
        for (int ks = 0; ks < 4; ks++) {
            int k0 = ks * 8;
            int rb = warp_m * 16;
            uint32_t af[4];
            af[0] = f2tf(as[(rb + g)     * TA_STR + k0 + tg]);
            af[1] = f2tf(as[(rb + g + 8) * TA_STR + k0 + tg]);
            af[2] = f2tf(as[(rb + g)     * TA_STR + k0 + tg + 4]);
            af[3] = f2tf(as[(rb + g + 8) * TA_STR + k0 + tg + 4]);
            uint32_t bf[4][2];
#pragma unroll
            for (int tn = 0; tn < 4; tn++) {
                int cb = warp_n * 32 + tn * 8;
                bf[tn][0] = __float_as_uint(bs[(k0 + tg)     * TB_STR + cb + g]);
                bf[tn][1] = __float_as_uint(bs[(k0 + tg + 4) * TB_STR + cb + g]);
            }
#pragma unroll
            for (int tn = 0; tn < 4; tn++) {
                asm volatile(
                    "mma.sync.aligned.m16n8k8.row.col.f32.tf32.tf32.f32 "
                    "{%0,%1,%2,%3}, {%4,%5,%6,%7}, {%8,%9}, {%0,%1,%2,%3};\n"
                    : "+f"(acc[tn][0]), "+f"(acc[tn][1]),
                      "+f"(acc[tn][2]), "+f"(acc[tn][3])
                    : "r"(af[0]), "r"(af[1]), "r"(af[2]), "r"(af[3]),
                      "r"(bf[tn][0]), "r"(bf[tn][1]));
            }
        }
        __syncthreads();
    }

    {
        int r0 = bm + warp_m * 16 + g;
        int r1 = r0 + 8;
#pragma unroll
        for (int tn = 0; tn < 4; tn++) {
            int c0 = bn + warp_n * 32 + tn * 8 + tg * 2;
#pragma unroll
            for (int half = 0; half < 2; half++) {
                int rr = half ? r1 : r0;
                if (rr >= M) continue;
                float v0 = acc[tn][half * 2 + 0];
                float v1 = acc[tn][half * 2 + 1];
                if (bias) { v0 += bias[c0]; v1 += bias[c0 + 1]; }
                if (act == 1) { v0 = gelu_exact(v0); v1 = gelu_exact(v1); }
                else if (act == 2) {
                    v0 = __uint_as_float(f2tf(v0));
                    v1 = __uint_as_float(f2tf(v1));
                }
                if (addsrc) {
                    v0 += addsrc[(size_t)rr * Nc + c0];
                    v1 += addsrc[(size_t)rr * Nc + c0 + 1];
                }
                C[(size_t)rr * Nc + c0]     = v0;
                C[(size_t)rr * Nc + c0 + 1] = v1;
            }
        }
    }
}

// ---------------- slot<-feature logits + competitive softmax over K ----------------
// logits against fn directly (q already carries Wq@Wk^T)
__global__ __launch_bounds__(512)
void qk_softmax_kernel(const float* __restrict__ q, const float* __restrict__ kmat,
                       float* __restrict__ attn) {
    __shared__ float qs[KK][DD];
    int b = blockIdx.x;
    int tid = threadIdx.x;
    const float4* qb4 = (const float4*)(q + (size_t)b * KK * DD);
    float4* qs4 = (float4*)&qs[0][0];
    for (int i = tid; i < KK * DD / 4; i += 512) qs4[i] = qb4[i];
    __syncthreads();
    int w = tid >> 5, lane = tid & 31;
    int n = blockIdx.y * 16 + w;
    if (n >= NN) return;
    const float4* kr4 = (const float4*)(kmat + ((size_t)b * NN + n) * DD);
    float p[KK];
#pragma unroll
    for (int s = 0; s < KK; s++) p[s] = 0.f;
#pragma unroll
    for (int it = 0; it < 6; it++) {
        int d4 = it * 32 + lane;
        float4 kv = kr4[d4];
#pragma unroll
        for (int s = 0; s < KK; s++) {
            const float4 qv = ((const float4*)qs[s])[d4];
            p[s] = fmaf(kv.x, qv.x, p[s]);
            p[s] = fmaf(kv.y, qv.y, p[s]);
            p[s] = fmaf(kv.z, qv.z, p[s]);
            p[s] = fmaf(kv.w, qv.w, p[s]);
        }
    }
#pragma unroll
    for (int s = 0; s < KK; s++)
        for (int off = 16; off; off >>= 1) p[s] += __shfl_xor_sync(0xffffffffu, p[s], off);
    float mx = -1e30f;
#pragma unroll
    for (int s = 0; s < KK; s++) { p[s] *= SCALE_QK; mx = fmaxf(mx, p[s]); }
    float tot = 0.f;
    float e[KK];
#pragma unroll
    for (int s = 0; s < KK; s++) { e[s] = expf(p[s] - mx); tot += e[s]; }
    float invt = 1.0f / tot;
    if (lane < KK) attn[((size_t)b * NN + n) * KK + lane] = e[lane] * invt;
}

// ---------------- mass[b,k] = max(sum_n attn[b,n,k], 1e-8) ----------------
__global__ void mass_kernel(const float* __restrict__ attn, float* __restrict__ mass) {
    int b = blockIdx.x, tid = threadIdx.x;
    float acc[KK];
#pragma unroll
    for (int s = 0; s < KK; s++) acc[s] = 0.f;
    for (int n = tid; n < NN; n += 256) {
        const float4* ar = (const float4*)(attn + ((size_t)b * NN + n) * KK);
        float4 a0 = ar[0], a1 = ar[1], a2 = ar[2];
        acc[0] += a0.x; acc[1] += a0.y; acc[2]  += a0.z; acc[3]  += a0.w;
        acc[4] += a1.x; acc[5] += a1.y; acc[6]  += a1.z; acc[7]  += a1.w;
        acc[8] += a2.x; acc[9] += a2.y; acc[10] += a2.z; acc[11] += a2.w;
    }
    __shared__ float red[KK][257];
#pragma unroll
    for (int s = 0; s < KK; s++) red[s][tid] = acc[s];
    __syncthreads();
    for (int off = 128; off > 0; off >>= 1) {
        if (tid < off)
#pragma unroll
            for (int s = 0; s < KK; s++) red[s][tid] += red[s][tid + off];
        __syncthreads();
    }
    if (tid < KK) mass[b * KK + tid] = fmaxf(red[tid][0], 1e-8f);
}

// ---------------- ub[b,k,d] = (sum_n attn[b,n,k]*fn[b,n,d]) / mass[b,k] ----------------
__global__ void updates_kernel(const float* __restrict__ attn, const float* __restrict__ v,
                               const float* __restrict__ mass, float* __restrict__ upd) {
    int b = blockIdx.x;
    int d = blockIdx.y * 128 + threadIdx.x;
    const float* vb = v + (size_t)b * NN * DD;
    const float* ab = attn + (size_t)b * NN * KK;
    float acc[KK];
#pragma unroll
    for (int s = 0; s < KK; s++) acc[s] = 0.f;
#pragma unroll 4
    for (int n = 0; n < NN; n++) {
        float vv = __ldg(vb + (size_t)n * DD + d);
        const float4* ar = (const float4*)(ab + (size_t)n * KK);
        float4 a0 = __ldg(ar), a1 = __ldg(ar + 1), a2 = __ldg(ar + 2);
        acc[0]  = fmaf(a0.x, vv, acc[0]);  acc[1]  = fmaf(a0.y, vv, acc[1]);
        acc[2]  = fmaf(a0.z, vv, acc[2]);  acc[3]  = fmaf(a0.w, vv, acc[3]);
        acc[4]  = fmaf(a1.x, vv, acc[4]);  acc[5]  = fmaf(a1.y, vv, acc[5]);
        acc[6]  = fmaf(a1.z, vv, acc[6]);  acc[7]  = fmaf(a1.w, vv, acc[7]);
        acc[8]  = fmaf(a2.x, vv, acc[8]);  acc[9]  = fmaf(a2.y, vv, acc[9]);
        acc[10] = fmaf(a2.z, vv, acc[10]); acc[11] = fmaf(a2.w, vv, acc[11]);
    }
#pragma unroll
    for (int s = 0; s < KK; s++)
        upd[((size_t)(b * KK + s)) * DD + d] = acc[s] / mass[b * KK + s];
}

// ---------------- tiny multi-head self-attention over the 12 slots ----------------
__global__ void blockattn_kernel(const float* __restrict__ qkv, float* __restrict__ obuf) {
    __shared__ float qs[KK][HD], ks[KK][HD], vs[KK][HD];
    __shared__ float sc[KK][KK], at[KK][KK];
    int b = blockIdx.x, h = blockIdx.y;
    int tid = threadIdx.x;     // 144 threads
    for (int idx = tid; idx < KK * HD; idx += 144) {
        int r = idx / HD, c = idx % HD;
        size_t base = ((size_t)(b * KK + r)) * (3 * DD) + h * HD + c;
        qs[r][c] = qkv[base];
        ks[r][c] = qkv[base + DD];
        vs[r][c] = qkv[base + 2 * DD];
    }
    __syncthreads();
    int i = tid / KK, j = tid % KK;
    {
        float s = 0.f;
#pragma unroll
        for (int d = 0; d < HD; d++) s = fmaf(qs[i][d], ks[j][d], s);
        sc[i][j] = s * SCALE_HD;
    }
    __syncthreads();
    {
        float mx = -1e30f;
#pragma unroll
        for (int jj = 0; jj < KK; jj++) mx = fmaxf(mx, sc[i][jj]);
        float tot = 0.f;
#pragma unroll
        for (int jj = 0; jj < KK; jj++) tot += expf(sc[i][jj] - mx);
        at[i][j] = expf(sc[i][j] - mx) / tot;
    }
    __syncthreads();
    for (int idx = tid; idx < KK * HD; idx += 144) {
        int r = idx / HD, d = idx % HD;
        float s = 0.f;
#pragma unroll
        for (int jj = 0; jj < KK; jj++) s = fmaf(at[r][jj], vs[jj][d], s);
        obuf[((size_t)(b * KK + r)) * DD + h * HD + d] = s;
    }
}

// ---------------- host orchestration ----------------
static float* symaddr(const void* sym) {
    void* p = nullptr;
    cudaGetSymbolAddress(&p, sym);
    return (float*)p;
}

extern "C" void kernel_launch(void* const* d_in, const int* in_sizes, int n_in,
                              void* d_out, int out_size) {
    const float* features  = (const float*)d_in[0];
    const float* slots_init= (const float*)d_in[1];
    const float* nf_g = (const float*)d_in[2];
    const float* nf_b = (const float*)d_in[3];
    const float* ns_g = (const float*)d_in[4];
    const float* ns_b = (const float*)d_in[5];
    const float* Wq   = (const float*)d_in[6];
    const float* Wk   = (const float*)d_in[7];
    const float* Wv   = (const float*)d_in[8];
    const float* mg   = (const float*)d_in[9];
    const float* mb   = (const float*)d_in[10];
    const float* mW1  = (const float*)d_in[11];
    const float* mb1  = (const float*)d_in[12];
    const float* mW2  = (const float*)d_in[13];
    const float* mb2  = (const float*)d_in[14];
    const float* b_ln1g = (const float*)d_in[15];
    const float* b_ln1b = (const float*)d_in[16];
    const float* b_Wqkv = (const float*)d_in[17];
    const float* b_bqkv = (const float*)d_in[18];
    const float* b_Wo   = (const float*)d_in[19];
    const float* b_bo   = (const float*)d_in[20];
    const float* b_ln2g = (const float*)d_in[21];
    const float* b_ln2b = (const float*)d_in[22];
    const float* b_W1   = (const float*)d_in[23];
    const float* b_b1   = (const float*)d_in[24];
    const float* b_W2   = (const float*)d_in[25];
    const float* b_b2   = (const float*)d_in[26];

    float* wtf  = symaddr(g_wtf);
    float* fn   = symaddr(g_fn);
    float* attn = symaddr(g_attn);
    float* sn   = symaddr(g_sn);
    float* qb   = symaddr(g_q);
    float* mass = symaddr(g_mass);
    float* ub   = symaddr(g_ub);
    float* upd  = symaddr(g_upd);
    float* h1   = symaddr(g_h1);
    float* qkv  = symaddr(g_qkv);
    float* ob   = symaddr(g_o);
    float* x1   = symaddr(g_x1);
    float* h2   = symaddr(g_h2);
    float* g1   = symaddr(g_g1);
    float* x2   = symaddr(g_x2);
    float* h3   = symaddr(g_h3);
    float* g2   = symaddr(g_g2);
    float* slots= symaddr(g_slots);

    auto roundw = [&](const float* src, float* dst, int n) {
        int n4 = n / 4;
        round_tf32_kernel<<<(n4 + 255) / 256, 256>>>((const float4*)src, (float4*)dst, n4);
    };
    // tf32 weight prep
    transpose_round_kernel<<<dim3(24, 24), dim3(32, 8)>>>(Wk, wtf + O_WKT);
    roundw(Wv,     wtf + O_WV,   W_SZ);
    roundw(mW1,    wtf + O_MW1,  MLP_SZ);
    roundw(mW2,    wtf + O_MW2,  MLP_SZ);
    roundw(b_Wqkv, wtf + O_BQKV, 3 * QKV_SZ);
    roundw(b_Wo,   wtf + O_BWO,  3 * W_SZ);
    roundw(b_W1,   wtf + O_BW1,  3 * MLP_SZ);
    roundw(b_W2,   wtf + O_BW2,  3 * MLP_SZ);

    auto gemmT = [](const float* A, const float* W, const float* bias, const float* add,
                    float* C, int M, int Nc, int Kc, int act) {
        dim3 grid(Nc / TBN, (M + TBM - 1) / TBM);
        gemm_tc32<<<grid, 128>>>(A, W, bias, add, C, M, Nc, Kc, act);
    };

    // one-time: Wqk = tf32(Wq @ Wk^T); fn = LN(features) (full fp32)
    gemmT(Wq, wtf + O_WKT, nullptr, nullptr, wtf + O_WQK, DD, DD, DD, 2);
    ln_kernel<<<BNROWS, 256>>>(features, nullptr, nf_g, nf_b, fn);
    cudaMemcpyAsync(slots, slots_init, (size_t)SROWS * DD * sizeof(float),
                    cudaMemcpyDeviceToDevice);

    dim3 qkgrid(BB, (NN + 15) / 16);

    for (int t = 0; t < TT; t++) {
        // slot->feature attention (restructured: q' = sn@Wqk ; logits vs fn)
        ln_kernel<<<SROWS, 256>>>(slots, nullptr, ns_g, ns_b, sn);
        gemmT(sn, wtf + O_WQK, nullptr, nullptr, qb, SROWS, DD, DD, 0);
        qk_softmax_kernel<<<qkgrid, 512>>>(qb, fn, attn);
        mass_kernel<<<BB, 256>>>(attn, mass);
        updates_kernel<<<dim3(BB, DD / 128), 128>>>(attn, fn, mass, ub);
        gemmT(ub, wtf + O_WV, nullptr, nullptr, upd, SROWS, DD, DD, 0);

        // transformer block on x = sn
        const float* ln1g = b_ln1g + (size_t)t * DD;
        const float* ln1b = b_ln1b + (size_t)t * DD;
        const float* Wqkvt = wtf + O_BQKV + (size_t)t * QKV_SZ;
        const float* bqkv = b_bqkv + (size_t)t * 3 * DD;
        const float* Wot  = wtf + O_BWO + (size_t)t * W_SZ;
        const float* bo   = b_bo   + (size_t)t * DD;
        const float* ln2g = b_ln2g + (size_t)t * DD;
        const float* ln2b = b_ln2b + (size_t)t * DD;
        const float* W1t  = wtf + O_BW1 + (size_t)t * MLP_SZ;
        const float* b1   = b_b1   + (size_t)t * 4 * DD;
        const float* W2t  = wtf + O_BW2 + (size_t)t * MLP_SZ;
        const float* b2   = b_b2   + (size_t)t * DD;

        ln_kernel<<<SROWS, 256>>>(sn, nullptr, ln1g, ln1b, h1);
        gemmT(h1, Wqkvt, bqkv, nullptr, qkv, SROWS, 3 * DD, DD, 0);
        blockattn_kernel<<<dim3(BB, HH), 144>>>(qkv, ob);
        gemmT(ob, Wot, bo, sn, x1, SROWS, DD, DD, 0);               // x1 = sn + o@Wo + bo
        ln_kernel<<<SROWS, 256>>>(x1, nullptr, ln2g, ln2b, h2);
        gemmT(h2, W1t, b1, nullptr, g1, SROWS, 4 * DD, DD, 1);      // gelu
        gemmT(g1, W2t, b2, x1, x2, SROWS, DD, 4 * DD, 0);           // slots_residual

        // mixer: slots += gelu(LN(upd + x2)@mW1 + mb1)@mW2 + mb2
        ln_kernel<<<SROWS, 256>>>(upd, x2, mg, mb, h3);
        gemmT(h3, wtf + O_MW1, mb1, nullptr, g2, SROWS, 4 * DD, DD, 1);
        gemmT(g2, wtf + O_MW2, mb2, slots, slots, SROWS, DD, 4 * DD, 0);
    }

    // final attention -> masks written straight into d_out tail
    float* out_slots = (float*)d_out;
    float* out_masks = out_slots + (size_t)SROWS * DD;
    ln_kernel<<<SROWS, 256>>>(slots, nullptr, ns_g, ns_b, sn);
    gemmT(sn, wtf + O_WQK, nullptr, nullptr, qb, SROWS, DD, DD, 0);
    qk_softmax_kernel<<<qkgrid, 512>>>(qb, fn, out_masks);
    cudaMemcpyAsync(out_slots, slots, (size_t)SROWS * DD * sizeof(float),
                    cudaMemcpyDeviceToDevice);
}

// round 8
// speedup vs baseline: 5.9231x; 2.1067x over previous
#include <cuda_runtime.h>
#include <math.h>
#include <stdint.h>

// ---------------- problem constants ----------------
#define BB 32
#define NN 1369
#define DD 768
#define KK 12
#define TT 3
#define HH 8
#define HD 96
#define BNROWS (BB * NN)          // 43808
#define SROWS  (BB * KK)          // 384
#define NB 148                    // persistent grid = #SMs (guaranteed co-resident)
#define NT 256
#define NCH 9
#define CH_TOK 153                // ceil(1369/9)
#define NUNITS (BB * NCH)         // 288
#define SCALE_QK 0.03608439182435161f
#define SCALE_HD 0.10206207261596575f

// ---------------- scratch (device globals) ----------------
__device__ float g_wkt [DD * DD];
__device__ float g_wqk [DD * DD];
__device__ float g_fn  [(size_t)BNROWS * DD];
__device__ float g_sn  [SROWS * DD];
__device__ float g_q   [SROWS * DD];
__device__ float g_pupd[(size_t)NUNITS * KK * DD];
__device__ float g_pmass[NUNITS * KK];
__device__ float g_ub  [SROWS * DD];
__device__ float g_upd [SROWS * DD];
__device__ float g_h1  [SROWS * DD];
__device__ float g_qkvb[SROWS * 3 * DD];
__device__ float g_ob  [SROWS * DD];
__device__ float g_x1  [SROWS * DD];
__device__ float g_h2  [SROWS * DD];
__device__ float g_g1  [SROWS * 4 * DD];
__device__ float g_x2  [SROWS * DD];
__device__ float g_h3  [SROWS * DD];
__device__ float g_g2  [SROWS * 4 * DD];
__device__ float g_slots[SROWS * DD];

__device__ int g_bar_count = 0;
__device__ int g_bar_gen   = 0;

// ---------------- helpers ----------------
__device__ __forceinline__ float gelu_exact(float x) {
    return 0.5f * x * (1.0f + erff(x * 0.70710678118654752f));
}
__device__ __forceinline__ uint32_t f2tf(float x) {
    uint32_t y;
    asm("cvt.rna.tf32.f32 %0, %1;" : "=r"(y) : "f"(x));
    return y;
}
__device__ __forceinline__ void cp16(void* smem_dst, const void* gmem_src, bool pred) {
    uint32_t s = (uint32_t)__cvta_generic_to_shared(smem_dst);
    int sz = pred ? 16 : 0;
    asm volatile("cp.async.ca.shared.global [%0], [%1], 16, %2;\n"
                 :: "r"(s), "l"(gmem_src), "r"(sz));
}
__device__ __forceinline__ void cp_commit() { asm volatile("cp.async.commit_group;\n"); }
__device__ __forceinline__ void cp_wait1()  { asm volatile("cp.async.wait_group 1;\n"); }
__device__ __forceinline__ void cp_waitall(){ asm volatile("cp.async.wait_all;\n" ::: "memory"); }

// ---------------- software grid barrier (all NB blocks resident) ----------------
__device__ __forceinline__ void gridbar() {
    __syncthreads();
    if (threadIdx.x == 0) {
        __threadfence();
        int gen = atomicAdd(&g_bar_gen, 0);
        if (atomicAdd(&g_bar_count, 1) == NB - 1) {
            g_bar_count = 0;
            __threadfence();
            atomicAdd(&g_bar_gen, 1);
        } else {
            while (atomicAdd(&g_bar_gen, 0) == gen) { __nanosleep(128); }
        }
        __threadfence();
    }
    __syncthreads();
}

// ---------------- LayerNorm: warp per row, out = LN(x [+ x2]) * g + b ----------------
__device__ void dev_ln(const float* __restrict__ x, const float* __restrict__ x2,
                       const float* __restrict__ gam, const float* __restrict__ bet,
                       float* __restrict__ out, int rows) {
    int warp = threadIdx.x >> 5, lane = threadIdx.x & 31;
    for (int r = blockIdx.x * 8 + warp; r < rows; r += NB * 8) {
        const float4* xr = (const float4*)(x + (size_t)r * DD);
        const float4* x2r = x2 ? (const float4*)(x2 + (size_t)r * DD) : nullptr;
        float4 v[6];
        float s = 0.f;
#pragma unroll
        for (int i = 0; i < 6; i++) {
            int d4 = lane + i * 32;
            float4 t = xr[d4];
            if (x2r) { float4 u = x2r[d4]; t.x += u.x; t.y += u.y; t.z += u.z; t.w += u.w; }
            v[i] = t;
            s += t.x + t.y + t.z + t.w;
        }
#pragma unroll
        for (int off = 16; off; off >>= 1) s += __shfl_xor_sync(0xffffffffu, s, off);
        float mean = s * (1.0f / DD);
        float s2 = 0.f;
#pragma unroll
        for (int i = 0; i < 6; i++) {
            float dx = v[i].x - mean, dy = v[i].y - mean, dz = v[i].z - mean, dw = v[i].w - mean;
            s2 += dx * dx + dy * dy + dz * dz + dw * dw;
        }
#pragma unroll
        for (int off = 16; off; off >>= 1) s2 += __shfl_xor_sync(0xffffffffu, s2, off);
        float inv = rsqrtf(s2 * (1.0f / DD) + 1e-5f);
        float4* o4 = (float4*)(out + (size_t)r * DD);
#pragma unroll
        for (int i = 0; i < 6; i++) {
            int d4 = lane + i * 32;
            float4 gv = ((const float4*)gam)[d4];
            float4 bv = ((const float4*)bet)[d4];
            float4 t;
            t.x = (v[i].x - mean) * inv * gv.x + bv.x;
            t.y = (v[i].y - mean) * inv * gv.y + bv.y;
            t.z = (v[i].z - mean) * inv * gv.z + bv.z;
            t.w = (v[i].w - mean) * inv * gv.w + bv.w;
            o4[d4] = t;
        }
    }
}

// ---------------- TF32 GEMM: 32x64 tiles, 8 warps, cvt both operands ----------------
// act: 0=none, 1=gelu
__device__ void dev_gemm(const float* __restrict__ A, const float* __restrict__ W,
                         const float* __restrict__ bias, const float* __restrict__ addsrc,
                         float* __restrict__ C, int M, int Nc, int Kc, int act,
                         float* s_u) {
    float* As = s_u;          // 2 * 32*36 = 2304
    float* Bs = s_u + 2304;   // 2 * 32*72 = 4608
    int tid = threadIdx.x, lane = tid & 31, warp = tid >> 5;
    int warp_m = warp >> 2, warp_n = warp & 3;
    int g = lane >> 2, tg = lane & 3;
    int ntn = Nc >> 6, ntm = (M + 31) >> 5;
    int nkt = Kc >> 5;
    int arow = tid >> 3, ac4 = tid & 7;      // A: 32 rows x 8 chunks
    int brow = tid >> 4, bc4 = tid & 15;     // B: 16 rows x 16 chunks (x2)

    for (int tix = blockIdx.x; tix < ntm * ntn; tix += NB) {
        int bm = (tix / ntn) << 5, bn = (tix % ntn) << 6;
        float acc[2][4];
#pragma unroll
        for (int i = 0; i < 2; i++)
#pragma unroll
            for (int j = 0; j < 4; j++) acc[i][j] = 0.f;

        __syncthreads();
        cp16(&As[arow * 36 + ac4 * 4], A + (size_t)(bm + arow) * Kc + ac4 * 4, (bm + arow) < M);
        cp16(&Bs[brow * 72 + bc4 * 4], W + (size_t)brow * Nc + bn + bc4 * 4, true);
        cp16(&Bs[(brow + 16) * 72 + bc4 * 4], W + (size_t)(brow + 16) * Nc + bn + bc4 * 4, true);
        cp_commit();

        for (int t = 0; t < nkt; t++) {
            if (t + 1 < nkt) {
                int k0 = (t + 1) << 5;
                int buf = (t + 1) & 1;
                cp16(&As[buf * 1152 + arow * 36 + ac4 * 4],
                     A + (size_t)(bm + arow) * Kc + k0 + ac4 * 4, (bm + arow) < M);
                cp16(&Bs[buf * 2304 + brow * 72 + bc4 * 4],
                     W + (size_t)(k0 + brow) * Nc + bn + bc4 * 4, true);
                cp16(&Bs[buf * 2304 + (brow + 16) * 72 + bc4 * 4],
                     W + (size_t)(k0 + brow + 16) * Nc + bn + bc4 * 4, true);
            }
            cp_commit();
            cp_wait1();
            __syncthreads();
            const float* as = As + (t & 1) * 1152;
            const float* bs = Bs + (t & 1) * 2304;
#pragma unroll
            for (int ks = 0; ks < 4; ks++) {
                int k0 = ks * 8;
                int rb = warp_m * 16;
                uint32_t af[4];
                af[0] = f2tf(as[(rb + g)     * 36 + k0 + tg]);
                af[1] = f2tf(as[(rb + g + 8) * 36 + k0 + tg]);
                af[2] = f2tf(as[(rb + g)     * 36 + k0 + tg + 4]);
                af[3] = f2tf(as[(rb + g + 8) * 36 + k0 + tg + 4]);
                uint32_t bf[2][2];
#pragma unroll
                for (int tn = 0; tn < 2; tn++) {
                    int cb = warp_n * 16 + tn * 8;
                    bf[tn][0] = f2tf(bs[(k0 + tg)     * 72 + cb + g]);
                    bf[tn][1] = f2tf(bs[(k0 + tg + 4) * 72 + cb + g]);
                }
#pragma unroll
                for (int tn = 0; tn < 2; tn++) {
                    asm volatile(
                        "mma.sync.aligned.m16n8k8.row.col.f32.tf32.tf32.f32 "
                        "{%0,%1,%2,%3}, {%4,%5,%6,%7}, {%8,%9}, {%0,%1,%2,%3};\n"
                        : "+f"(acc[tn][0]), "+f"(acc[tn][1]),
                          "+f"(acc[tn][2]), "+f"(acc[tn][3])
                        : "r"(af[0]), "r"(af[1]), "r"(af[2]), "r"(af[3]),
                          "r"(bf[tn][0]), "r"(bf[tn][1]));
                }
            }
            __syncthreads();
        }
        cp_waitall();

        int r0 = bm + warp_m * 16 + g;
#pragma unroll
        for (int tn = 0; tn < 2; tn++) {
            int c0 = bn + warp_n * 16 + tn * 8 + tg * 2;
#pragma unroll
            for (int half = 0; half < 2; half++) {
                int rr = r0 + half * 8;
                if (rr >= M) continue;
                float v0 = acc[tn][half * 2 + 0];
                float v1 = acc[tn][half * 2 + 1];
                if (bias) { v0 += bias[c0]; v1 += bias[c0 + 1]; }
                if (act == 1) { v0 = gelu_exact(v0); v1 = gelu_exact(v1); }
                if (addsrc) {
                    v0 += addsrc[(size_t)rr * Nc + c0];
                    v1 += addsrc[(size_t)rr * Nc + c0 + 1];
                }
                C[(size_t)rr * Nc + c0]     = v0;
                C[(size_t)rr * Nc + c0 + 1] = v1;
            }
        }
    }
    __syncthreads();
}

// ---------------- fused slot attention: logits+softmax+mass+attn^T@fn ----------------
// write_upd=1: accumulate partial updates/mass. write_upd=0: write masks only.
__device__ void dev_fused(const float* __restrict__ qmat, const float* __restrict__ fn,
                          float* __restrict__ pupd, float* __restrict__ pmass,
                          float* __restrict__ masks, int write_upd, float* s_u) {
    float* qs      = s_u;            // 9216
    float* at      = s_u + 9216;     // 96
    float* massacc = s_u + 9312;     // 12
    int tid = threadIdx.x, lane = tid & 31, warp = tid >> 5;
    const float4* qsv = (const float4*)qs;

    for (int u = blockIdx.x; u < NUNITS; u += NB) {
        int b = u % BB, ch = u / BB;
        int n0 = ch * CH_TOK;
        int n1 = n0 + CH_TOK; if (n1 > NN) n1 = NN;

        __syncthreads();
        {
            const float4* qb4 = (const float4*)(qmat + (size_t)b * KK * DD);
            float4* qd = (float4*)qs;
            for (int i = tid; i < KK * DD / 4; i += NT) qd[i] = qb4[i];
        }
        if (tid < KK) massacc[tid] = 0.f;
        float acc[KK][3];
#pragma unroll
        for (int k = 0; k < KK; k++) { acc[k][0] = 0.f; acc[k][1] = 0.f; acc[k][2] = 0.f; }
        __syncthreads();

        const float4* fn4 = (const float4*)fn;
        for (int base = n0; base < n1; base += 8) {
            int n = base + warp;
            bool valid = n < n1;
            float mine = 0.f;
            if (valid) {
                float p[KK];
#pragma unroll
                for (int s = 0; s < KK; s++) p[s] = 0.f;
                size_t rb4 = ((size_t)b * NN + n) * (DD / 4);
#pragma unroll
                for (int it = 0; it < 6; it++) {
                    int d4 = it * 32 + lane;
                    float4 kv = fn4[rb4 + d4];
#pragma unroll
                    for (int s = 0; s < KK; s++) {
                        float4 qv = qsv[s * (DD / 4) + d4];
                        p[s] = fmaf(kv.x, qv.x, p[s]);
                        p[s] = fmaf(kv.y, qv.y, p[s]);
                        p[s] = fmaf(kv.z, qv.z, p[s]);
                        p[s] = fmaf(kv.w, qv.w, p[s]);
                    }
                }
#pragma unroll
                for (int s = 0; s < KK; s++)
#pragma unroll
                    for (int off = 16; off; off >>= 1)
                        p[s] += __shfl_xor_sync(0xffffffffu, p[s], off);
                float mx = -1e30f;
#pragma unroll
                for (int s = 0; s < KK; s++) { p[s] *= SCALE_QK; mx = fmaxf(mx, p[s]); }
                float tot = 0.f;
                float e[KK];
#pragma unroll
                for (int s = 0; s < KK; s++) { e[s] = expf(p[s] - mx); tot += e[s]; }
                float invt = 1.0f / tot;
#pragma unroll
                for (int s = 0; s < KK; s++) if (lane == s) mine = e[s] * invt;
            }
            if (lane < KK) at[warp * KK + lane] = mine;
            if (write_upd) {
                if (valid && lane < KK) atomicAdd(&massacc[lane], mine);
            } else {
                if (valid && lane < KK)
                    masks[((size_t)b * NN + n) * KK + lane] = mine;
            }
            __syncthreads();
            if (write_upd) {
                int nv = n1 - base; if (nv > 8) nv = 8;
                const float* fb = fn + ((size_t)b * NN + base) * DD;
                for (int j = 0; j < nv; j++) {
                    float f0 = fb[(size_t)j * DD + tid];
                    float f1 = fb[(size_t)j * DD + tid + 256];
                    float f2 = fb[(size_t)j * DD + tid + 512];
#pragma unroll
                    for (int k = 0; k < KK; k++) {
                        float a = at[j * KK + k];
                        acc[k][0] = fmaf(a, f0, acc[k][0]);
                        acc[k][1] = fmaf(a, f1, acc[k][1]);
                        acc[k][2] = fmaf(a, f2, acc[k][2]);
                    }
                }
            }
            __syncthreads();
        }
        if (write_upd) {
            float* pu = pupd + (size_t)u * KK * DD;
#pragma unroll
            for (int k = 0; k < KK; k++) {
                pu[k * DD + tid]       = acc[k][0];
                pu[k * DD + tid + 256] = acc[k][1];
                pu[k * DD + tid + 512] = acc[k][2];
            }
            if (tid < KK) pmass[u * KK + tid] = massacc[tid];
        }
        __syncthreads();
    }
    __syncthreads();
}

// ---------------- reduce partials: ub = (sum_ch pupd) / max(sum_ch pmass, eps) ----------------
__device__ void dev_reduce(const float* __restrict__ pupd, const float* __restrict__ pmass,
                           float* __restrict__ ub) {
    int tid = threadIdx.x;
    for (int r = blockIdx.x; r < SROWS; r += NB) {
        int b = r / KK, k = r % KK;
        float m = 0.f;
#pragma unroll
        for (int ch = 0; ch < NCH; ch++) m += pmass[(ch * BB + b) * KK + k];
        float inv = 1.0f / fmaxf(m, 1e-8f);
#pragma unroll
        for (int c = 0; c < 3; c++) {
            int d = tid + c * 256;
            float s = 0.f;
#pragma unroll
            for (int ch = 0; ch < NCH; ch++)
                s += pupd[(size_t)(ch * BB + b) * KK * DD + k * DD + d];
            ub[(size_t)r * DD + d] = s * inv;
        }
    }
}

// ---------------- tiny multi-head self-attention over the 12 slots ----------------
__device__ void dev_blockattn(const float* __restrict__ qkv, float* __restrict__ obuf,
                              float* s_u) {
    float* qs = s_u;            // 1152
    float* ks = s_u + 1152;
    float* vs = s_u + 2304;
    float* sc = s_u + 3456;     // 144
    float* at = s_u + 3600;     // 144
    int tid = threadIdx.x;
    for (int u = blockIdx.x; u < BB * HH; u += NB) {
        int b = u >> 3, h = u & 7;
        __syncthreads();
        for (int idx = tid; idx < KK * HD; idx += NT) {
            int r = idx / HD, c = idx % HD;
            size_t base = ((size_t)(b * KK + r)) * (3 * DD) + h * HD + c;
            qs[r * HD + c] = qkv[base];
            ks[r * HD + c] = qkv[base + DD];
            vs[r * HD + c] = qkv[base + 2 * DD];
        }
        __syncthreads();
        if (tid < 144) {
            int i = tid / KK, j = tid % KK;
            float s = 0.f;
#pragma unroll
            for (int d = 0; d < HD; d++) s = fmaf(qs[i * HD + d], ks[j * HD + d], s);
            sc[i * KK + j] = s * SCALE_HD;
        }
        __syncthreads();
        if (tid < 144) {
            int i = tid / KK, j = tid % KK;
            float mx = -1e30f;
#pragma unroll
            for (int jj = 0; jj < KK; jj++) mx = fmaxf(mx, sc[i * KK + jj]);
            float tot = 0.f;
#pragma unroll
            for (int jj = 0; jj < KK; jj++) tot += expf(sc[i * KK + jj] - mx);
            at[i * KK + j] = expf(sc[i * KK + j] - mx) / tot;
        }
        __syncthreads();
        for (int idx = tid; idx < KK * HD; idx += NT) {
            int r = idx / HD, d = idx % HD;
            float s = 0.f;
#pragma unroll
            for (int jj = 0; jj < KK; jj++) s = fmaf(at[r * KK + jj], vs[jj * HD + d], s);
            obuf[((size_t)(b * KK + r)) * DD + h * HD + d] = s;
        }
        __syncthreads();
    }
    __syncthreads();
}

// ---------------- transpose 768x768 (raw, no rounding; gemm cvts) ----------------
__device__ void dev_transpose(const float* __restrict__ in, float* __restrict__ out,
                              float* s_u) {
    float* tile = s_u;   // 32*33 = 1056
    int tx = threadIdx.x & 31, ty = threadIdx.x >> 5;   // 32 x 8
    for (int tix = blockIdx.x; tix < 24 * 24; tix += NB) {
        int bx = (tix % 24) * 32, by = (tix / 24) * 32;
        __syncthreads();
#pragma unroll
        for (int dy = 0; dy < 4; dy++)
            tile[(ty + dy * 8) * 33 + tx] = in[(size_t)(by + ty + dy * 8) * DD + bx + tx];
        __syncthreads();
#pragma unroll
        for (int dy = 0; dy < 4; dy++)
            out[(size_t)(bx + ty + dy * 8) * DD + by + tx] = tile[tx * 33 + ty + dy * 8];
    }
    __syncthreads();
}

__device__ void dev_copy(float* __restrict__ dst, const float* __restrict__ src, int n4) {
    for (int i = blockIdx.x * NT + threadIdx.x; i < n4; i += NB * NT)
        ((float4*)dst)[i] = ((const float4*)src)[i];
}

// ---------------- the megakernel ----------------
__global__ __launch_bounds__(NT)
void mega_kernel(const float* features, const float* slots_init,
                 const float* nf_g, const float* nf_b,
                 const float* ns_g, const float* ns_b,
                 const float* Wq, const float* Wk, const float* Wv,
                 const float* mg, const float* mb,
                 const float* mW1, const float* mb1,
                 const float* mW2, const float* mb2,
                 const float* b_ln1g, const float* b_ln1b,
                 const float* b_Wqkv, const float* b_bqkv,
                 const float* b_Wo, const float* b_bo,
                 const float* b_ln2g, const float* b_ln2b,
                 const float* b_W1, const float* b_b1,
                 const float* b_W2, const float* b_b2,
                 float* out) {
    __shared__ __align__(16) float s_u[9728];   // 38.9 KB union

    // phase 0: transpose Wk, LN(features), copy slots
    dev_transpose(Wk, g_wkt, s_u);
    dev_ln(features, nullptr, nf_g, nf_b, g_fn, BNROWS);
    dev_copy(g_slots, slots_init, SROWS * DD / 4);
    gridbar();
    // phase 0b: Wqk = Wq @ Wk^T   (tf32 effective at use)
    dev_gemm(Wq, g_wkt, nullptr, nullptr, g_wqk, DD, DD, DD, 0, s_u);
    gridbar();

    for (int t = 0; t < TT; t++) {
        const float* ln1g = b_ln1g + (size_t)t * DD;
        const float* ln1b = b_ln1b + (size_t)t * DD;
        const float* Wqkv = b_Wqkv + (size_t)t * DD * 3 * DD;
        const float* bqkv = b_bqkv + (size_t)t * 3 * DD;
        const float* Wo   = b_Wo   + (size_t)t * DD * DD;
        const float* bo   = b_bo   + (size_t)t * DD;
        const float* ln2g = b_ln2g + (size_t)t * DD;
        const float* ln2b = b_ln2b + (size_t)t * DD;
        const float* W1   = b_W1   + (size_t)t * DD * 4 * DD;
        const float* b1   = b_b1   + (size_t)t * 4 * DD;
        const float* W2   = b_W2   + (size_t)t * 4 * DD * DD;
        const float* b2   = b_b2   + (size_t)t * DD;

        dev_ln(g_slots, nullptr, ns_g, ns_b, g_sn, SROWS);
        gridbar();
        dev_gemm(g_sn, g_wqk, nullptr, nullptr, g_q, SROWS, DD, DD, 0, s_u);
        dev_ln(g_sn, nullptr, ln1g, ln1b, g_h1, SROWS);
        gridbar();
        dev_fused(g_q, g_fn, g_pupd, g_pmass, nullptr, 1, s_u);
        dev_gemm(g_h1, Wqkv, bqkv, nullptr, g_qkvb, SROWS, 3 * DD, DD, 0, s_u);
        gridbar();
        dev_reduce(g_pupd, g_pmass, g_ub);
        dev_blockattn(g_qkvb, g_ob, s_u);
        gridbar();
        dev_gemm(g_ub, Wv, nullptr, nullptr, g_upd, SROWS, DD, DD, 0, s_u);
        dev_gemm(g_ob, Wo, bo, g_sn, g_x1, SROWS, DD, DD, 0, s_u);
        gridbar();
        dev_ln(g_x1, nullptr, ln2g, ln2b, g_h2, SROWS);
        gridbar();
        dev_gemm(g_h2, W1, b1, nullptr, g_g1, SROWS, 4 * DD, DD, 1, s_u);
        gridbar();
        dev_gemm(g_g1, W2, b2, g_x1, g_x2, SROWS, DD, 4 * DD, 0, s_u);
        gridbar();
        dev_ln(g_upd, g_x2, mg, mb, g_h3, SROWS);
        gridbar();
        dev_gemm(g_h3, mW1, mb1, nullptr, g_g2, SROWS, 4 * DD, DD, 1, s_u);
        gridbar();
        dev_gemm(g_g2, mW2, mb2, g_slots, g_slots, SROWS, DD, 4 * DD, 0, s_u);
        gridbar();
    }

    // final attention -> masks; slots -> out
    dev_ln(g_slots, nullptr, ns_g, ns_b, g_sn, SROWS);
    gridbar();
    dev_gemm(g_sn, g_wqk, nullptr, nullptr, g_q, SROWS, DD, DD, 0, s_u);
    dev_copy(out, g_slots, SROWS * DD / 4);
    gridbar();
    dev_fused(g_q, g_fn, nullptr, nullptr, out + (size_t)SROWS * DD, 0, s_u);
}

// ---------------- host ----------------
extern "C" void kernel_launch(void* const* d_in, const int* in_sizes, int n_in,
                              void* d_out, int out_size) {
    const float* features  = (const float*)d_in[0];
    const float* slots_init= (const float*)d_in[1];
    const float* nf_g = (const float*)d_in[2];
    const float* nf_b = (const float*)d_in[3];
    const float* ns_g = (const float*)d_in[4];
    const float* ns_b = (const float*)d_in[5];
    const float* Wq   = (const float*)d_in[6];
    const float* Wk   = (const float*)d_in[7];
    const float* Wv   = (const float*)d_in[8];
    const float* mg   = (const float*)d_in[9];
    const float* mb   = (const float*)d_in[10];
    const float* mW1  = (const float*)d_in[11];
    const float* mb1  = (const float*)d_in[12];
    const float* mW2  = (const float*)d_in[13];
    const float* mb2  = (const float*)d_in[14];
    const float* b_ln1g = (const float*)d_in[15];
    const float* b_ln1b = (const float*)d_in[16];
    const float* b_Wqkv = (const float*)d_in[17];
    const float* b_bqkv = (const float*)d_in[18];
    const float* b_Wo   = (const float*)d_in[19];
    const float* b_bo   = (const float*)d_in[20];
    const float* b_ln2g = (const float*)d_in[21];
    const float* b_ln2b = (const float*)d_in[22];
    const float* b_W1   = (const float*)d_in[23];
    const float* b_b1   = (const float*)d_in[24];
    const float* b_W2   = (const float*)d_in[25];
    const float* b_b2   = (const float*)d_in[26];

    mega_kernel<<<NB, NT>>>(features, slots_init, nf_g, nf_b, ns_g, ns_b,
                            Wq, Wk, Wv, mg, mb, mW1, mb1, mW2, mb2,
                            b_ln1g, b_ln1b, b_Wqkv, b_bqkv, b_Wo, b_bo,
                            b_ln2g, b_ln2b, b_W1, b_b1, b_W2, b_b2,
                            (float*)d_out);
}

// round 10
// speedup vs baseline: 5.9625x; 1.0066x over previous
#include <cuda_runtime.h>
#include <math.h>
#include <stdint.h>

// ---------------- problem constants ----------------
#define BB 32
#define NN 1369
#define DD 768
#define KK 12
#define TT 3
#define HH 8
#define HD 96
#define BNROWS (BB * NN)          // 43808
#define SROWS  (BB * KK)          // 384
#define NB 148                    // persistent grid = #SMs
#define NT 256
#define NCH 9
#define CH_TOK 153                // ceil(1369/9)
#define NUNITS (BB * NCH)         // 288
#define TPW 4                     // tokens per warp in fused logits
#define GRP 32                    // tokens per group (8 warps * 4)
#define SCALE_QK 0.03608439182435161f
#define SCALE_HD 0.10206207261596575f

// ---------------- scratch (device globals) ----------------
__device__ float g_wkt [DD * DD];
__device__ float g_wqk [DD * DD];
__device__ float g_fn  [(size_t)BNROWS * DD];
__device__ float g_sn  [SROWS * DD];
__device__ float g_q   [SROWS * DD];
__device__ float g_pupd[(size_t)NUNITS * KK * DD];
__device__ float g_pmass[NUNITS * KK];
__device__ float g_ub  [SROWS * DD];
__device__ float g_upd [SROWS * DD];
__device__ float g_h1  [SROWS * DD];
__device__ float g_qkvb[SROWS * 3 * DD];
__device__ float g_ob  [SROWS * DD];
__device__ float g_x1  [SROWS * DD];
__device__ float g_h2  [SROWS * DD];
__device__ float g_g1  [SROWS * 4 * DD];
__device__ float g_x2  [SROWS * DD];
__device__ float g_h3  [SROWS * DD];
__device__ float g_g2  [SROWS * 4 * DD];
__device__ float g_slots[SROWS * DD];

__device__ int g_bar_count = 0;
__device__ int g_bar_gen   = 0;

// ---------------- helpers ----------------
__device__ __forceinline__ float gelu_exact(float x) {
    return 0.5f * x * (1.0f + erff(x * 0.70710678118654752f));
}
__device__ __forceinline__ uint32_t f2tf(float x) {
    uint32_t y;
    asm("cvt.rna.tf32.f32 %0, %1;" : "=r"(y) : "f"(x));
    return y;
}
__device__ __forceinline__ void cp16(void* smem_dst, const void* gmem_src, bool pred) {
    uint32_t s = (uint32_t)__cvta_generic_to_shared(smem_dst);
    int sz = pred ? 16 : 0;
    asm volatile("cp.async.ca.shared.global [%0], [%1], 16, %2;\n"
                 :: "r"(s), "l"(gmem_src), "r"(sz));
}
__device__ __forceinline__ void cp_commit() { asm volatile("cp.async.commit_group;\n"); }
__device__ __forceinline__ void cp_wait1()  { asm volatile("cp.async.wait_group 1;\n"); }
__device__ __forceinline__ void cp_waitall(){ asm volatile("cp.async.wait_all;\n" ::: "memory"); }

// ---------------- software grid barrier ----------------
__device__ __forceinline__ void gridbar() {
    __syncthreads();
    if (threadIdx.x == 0) {
        __threadfence();
        int gen = atomicAdd(&g_bar_gen, 0);
        if (atomicAdd(&g_bar_count, 1) == NB - 1) {
            g_bar_count = 0;
            __threadfence();
            atomicAdd(&g_bar_gen, 1);
        } else {
            while (atomicAdd(&g_bar_gen, 0) == gen) { __nanosleep(128); }
        }
        __threadfence();
    }
    __syncthreads();
}

// ---------------- LayerNorm: warp per row ----------------
__device__ void dev_ln(const float* __restrict__ x, const float* __restrict__ x2,
                       const float* __restrict__ gam, const float* __restrict__ bet,
                       float* __restrict__ out, int rows) {
    int warp = threadIdx.x >> 5, lane = threadIdx.x & 31;
    for (int r = blockIdx.x * 8 + warp; r < rows; r += NB * 8) {
        const float4* xr = (const float4*)(x + (size_t)r * DD);
        const float4* x2r = x2 ? (const float4*)(x2 + (size_t)r * DD) : nullptr;
        float4 v[6];
        float s = 0.f;
#pragma unroll
        for (int i = 0; i < 6; i++) {
            int d4 = lane + i * 32;
            float4 t = xr[d4];
            if (x2r) { float4 u = x2r[d4]; t.x += u.x; t.y += u.y; t.z += u.z; t.w += u.w; }
            v[i] = t;
            s += t.x + t.y + t.z + t.w;
        }
#pragma unroll
        for (int off = 16; off; off >>= 1) s += __shfl_xor_sync(0xffffffffu, s, off);
        float mean = s * (1.0f / DD);
        float s2 = 0.f;
#pragma unroll
        for (int i = 0; i < 6; i++) {
            float dx = v[i].x - mean, dy = v[i].y - mean, dz = v[i].z - mean, dw = v[i].w - mean;
            s2 += dx * dx + dy * dy + dz * dz + dw * dw;
        }
#pragma unroll
        for (int off = 16; off; off >>= 1) s2 += __shfl_xor_sync(0xffffffffu, s2, off);
        float inv = rsqrtf(s2 * (1.0f / DD) + 1e-5f);
        float4* o4 = (float4*)(out + (size_t)r * DD);
#pragma unroll
        for (int i = 0; i < 6; i++) {
            int d4 = lane + i * 32;
            float4 gv = ((const float4*)gam)[d4];
            float4 bv = ((const float4*)bet)[d4];
            float4 t;
            t.x = (v[i].x - mean) * inv * gv.x + bv.x;
            t.y = (v[i].y - mean) * inv * gv.y + bv.y;
            t.z = (v[i].z - mean) * inv * gv.z + bv.z;
            t.w = (v[i].w - mean) * inv * gv.w + bv.w;
            o4[d4] = t;
        }
    }
}

// ---------------- TF32 GEMM: 32x64 tiles, 8 warps ----------------
__device__ void dev_gemm(const float* __restrict__ A, const float* __restrict__ W,
                         const float* __restrict__ bias, const float* __restrict__ addsrc,
                         float* __restrict__ C, int M, int Nc, int Kc, int act,
                         float* s_u) {
    float* As = s_u;
    float* Bs = s_u + 2304;
    int tid = threadIdx.x, lane = tid & 31, warp = tid >> 5;
    int warp_m = warp >> 2, warp_n = warp & 3;
    int g = lane >> 2, tg = lane & 3;
    int ntn = Nc >> 6, ntm = (M + 31) >> 5;
    int nkt = Kc >> 5;
    int arow = tid >> 3, ac4 = tid & 7;
    int brow = tid >> 4, bc4 = tid & 15;

    for (int tix = blockIdx.x; tix < ntm * ntn; tix += NB) {
        int bm = (tix / ntn) << 5, bn = (tix % ntn) << 6;
        float acc[2][4];
#pragma unroll
        for (int i = 0; i < 2; i++)
#pragma unroll
            for (int j = 0; j < 4; j++) acc[i][j] = 0.f;

        __syncthreads();
        cp16(&As[arow * 36 + ac4 * 4], A + (size_t)(bm + arow) * Kc + ac4 * 4, (bm + arow) < M);
        cp16(&Bs[brow * 72 + bc4 * 4], W + (size_t)brow * Nc + bn + bc4 * 4, true);
        cp16(&Bs[(brow + 16) * 72 + bc4 * 4], W + (size_t)(brow + 16) * Nc + bn + bc4 * 4, true);
        cp_commit();

        for (int t = 0; t < nkt; t++) {
            if (t + 1 < nkt) {
                int k0 = (t + 1) << 5;
                int buf = (t + 1) & 1;
                cp16(&As[buf * 1152 + arow * 36 + ac4 * 4],
                     A + (size_t)(bm + arow) * Kc + k0 + ac4 * 4, (bm + arow) < M);
                cp16(&Bs[buf * 2304 + brow * 72 + bc4 * 4],
                     W + (size_t)(k0 + brow) * Nc + bn + bc4 * 4, true);
                cp16(&Bs[buf * 2304 + (brow + 16) * 72 + bc4 * 4],
                     W + (size_t)(k0 + brow + 16) * Nc + bn + bc4 * 4, true);
            }
            cp_commit();
            cp_wait1();
            __syncthreads();
            const float* as = As + (t & 1) * 1152;
            const float* bs = Bs + (t & 1) * 2304;
#pragma unroll
            for (int ks = 0; ks < 4; ks++) {
                int k0 = ks * 8;
                int rb = warp_m * 16;
                uint32_t af[4];
                af[0] = f2tf(as[(rb + g)     * 36 + k0 + tg]);
                af[1] = f2tf(as[(rb + g + 8) * 36 + k0 + tg]);
                af[2] = f2tf(as[(rb + g)     * 36 + k0 + tg + 4]);
                af[3] = f2tf(as[(rb + g + 8) * 36 + k0 + tg + 4]);
                uint32_t bf[2][2];
#pragma unroll
                for (int tn = 0; tn < 2; tn++) {
                    int cb = warp_n * 16 + tn * 8;
                    bf[tn][0] = f2tf(bs[(k0 + tg)     * 72 + cb + g]);
                    bf[tn][1] = f2tf(bs[(k0 + tg + 4) * 72 + cb + g]);
                }
#pragma unroll
                for (int tn = 0; tn < 2; tn++) {
                    asm volatile(
                        "mma.sync.aligned.m16n8k8.row.col.f32.tf32.tf32.f32 "
                        "{%0,%1,%2,%3}, {%4,%5,%6,%7}, {%8,%9}, {%0,%1,%2,%3};\n"
                        : "+f"(acc[tn][0]), "+f"(acc[tn][1]),
                          "+f"(acc[tn][2]), "+f"(acc[tn][3])
                        : "r"(af[0]), "r"(af[1]), "r"(af[2]), "r"(af[3]),
                          "r"(bf[tn][0]), "r"(bf[tn][1]));
                }
            }
            __syncthreads();
        }
        cp_waitall();

        int r0 = bm + warp_m * 16 + g;
#pragma unroll
        for (int tn = 0; tn < 2; tn++) {
            int c0 = bn + warp_n * 16 + tn * 8 + tg * 2;
#pragma unroll
            for (int half = 0; half < 2; half++) {
                int rr = r0 + half * 8;
                if (rr >= M) continue;
                float v0 = acc[tn][half * 2 + 0];
                float v1 = acc[tn][half * 2 + 1];
                if (bias) { v0 += bias[c0]; v1 += bias[c0 + 1]; }
                if (act == 1) { v0 = gelu_exact(v0); v1 = gelu_exact(v1); }
                if (addsrc) {
                    v0 += addsrc[(size_t)rr * Nc + c0];
                    v1 += addsrc[(size_t)rr * Nc + c0 + 1];
                }
                C[(size_t)rr * Nc + c0]     = v0;
                C[(size_t)rr * Nc + c0 + 1] = v1;
            }
        }
    }
    __syncthreads();
}

// ---------------- fused slot attention, 4 tokens/warp ----------------
__device__ void dev_fused(const float* __restrict__ qmat, const float* __restrict__ fn,
                          float* __restrict__ pupd, float* __restrict__ pmass,
                          float* __restrict__ masks, int write_upd, float* s_u) {
    float* qs      = s_u;            // 9216
    float* at      = s_u + 9216;     // GRP*KK = 384
    float* massacc = s_u + 9600;     // 12
    int tid = threadIdx.x, lane = tid & 31, warp = tid >> 5;
    const float4* qsv = (const float4*)qs;
    const float4* fn4 = (const float4*)fn;

    for (int u = blockIdx.x; u < NUNITS; u += NB) {
        int b = u % BB, ch = u / BB;
        int n0 = ch * CH_TOK;
        int n1 = n0 + CH_TOK; if (n1 > NN) n1 = NN;

        __syncthreads();
        {
            const float4* qb4 = (const float4*)(qmat + (size_t)b * KK * DD);
            float4* qd = (float4*)qs;
            for (int i = tid; i < KK * DD / 4; i += NT) qd[i] = qb4[i];
        }
        if (tid < KK) massacc[tid] = 0.f;
        float acc0[KK], acc1[KK], acc2[KK];
#pragma unroll
        for (int k = 0; k < KK; k++) { acc0[k] = 0.f; acc1[k] = 0.f; acc2[k] = 0.f; }
        __syncthreads();

        for (int base = n0; base < n1; base += GRP) {
            // ---- logits for this warp's 4 tokens ----
            int ntok[TPW];
            bool valid[TPW];
            size_t rb4[TPW];
#pragma unroll
            for (int tk = 0; tk < TPW; tk++) {
                ntok[tk] = base + warp * TPW + tk;
                valid[tk] = ntok[tk] < n1;
                int rowc = valid[tk] ? ntok[tk] : (n1 - 1);
                rb4[tk] = ((size_t)b * NN + rowc) * (DD / 4);
            }
            float p[TPW][KK];
#pragma unroll
            for (int tk = 0; tk < TPW; tk++)
#pragma unroll
                for (int s = 0; s < KK; s++) p[tk][s] = 0.f;
#pragma unroll
            for (int it = 0; it < 6; it++) {
                int d4 = it * 32 + lane;
                float4 kv[TPW];
#pragma unroll
                for (int tk = 0; tk < TPW; tk++) kv[tk] = fn4[rb4[tk] + d4];
#pragma unroll
                for (int s = 0; s < KK; s++) {
                    float4 qv = qsv[s * (DD / 4) + d4];
#pragma unroll
                    for (int tk = 0; tk < TPW; tk++) {
                        p[tk][s] = fmaf(kv[tk].x, qv.x, p[tk][s]);
                        p[tk][s] = fmaf(kv[tk].y, qv.y, p[tk][s]);
                        p[tk][s] = fmaf(kv[tk].z, qv.z, p[tk][s]);
                        p[tk][s] = fmaf(kv[tk].w, qv.w, p[tk][s]);
                    }
                }
            }
#pragma unroll
            for (int tk = 0; tk < TPW; tk++)
#pragma unroll
                for (int s = 0; s < KK; s++)
#pragma unroll
                    for (int off = 16; off; off >>= 1)
                        p[tk][s] += __shfl_xor_sync(0xffffffffu, p[tk][s], off);
#pragma unroll
            for (int tk = 0; tk < TPW; tk++) {
                float mx = -1e30f;
#pragma unroll
                for (int s = 0; s < KK; s++) { p[tk][s] *= SCALE_QK; mx = fmaxf(mx, p[tk][s]); }
                float tot = 0.f;
                float e[KK];
#pragma unroll
                for (int s = 0; s < KK; s++) { e[s] = expf(p[tk][s] - mx); tot += e[s]; }
                float invt = 1.0f / tot;
                float mine = (valid[tk] && lane < KK) ? e[lane] * invt : 0.f;
                if (lane < KK) {
                    at[(warp * TPW + tk) * KK + lane] = mine;
                    if (write_upd) {
                        if (valid[tk]) atomicAdd(&massacc[lane], mine);
                    } else if (valid[tk]) {
                        masks[((size_t)b * NN + ntok[tk]) * KK + lane] = mine;
                    }
                }
            }
            __syncthreads();
            // ---- accumulate partial attn^T @ fn over this 32-token group ----
            if (write_upd) {
                int gmax = n1 - base; if (gmax > GRP) gmax = GRP;
                const float* fb = fn + ((size_t)b * NN + base) * DD;
#pragma unroll 4
                for (int j = 0; j < gmax; j++) {
                    float f0 = fb[(size_t)j * DD + tid];
                    float f1 = fb[(size_t)j * DD + tid + 256];
                    float f2 = fb[(size_t)j * DD + tid + 512];
                    const float* aj = at + j * KK;
#pragma unroll
                    for (int k = 0; k < KK; k++) {
                        float a = aj[k];
                        acc0[k] = fmaf(a, f0, acc0[k]);
                        acc1[k] = fmaf(a, f1, acc1[k]);
                        acc2[k] = fmaf(a, f2, acc2[k]);
                    }
                }
            }
            __syncthreads();
        }
        if (write_upd) {
            float* pu = pupd + (size_t)u * KK * DD;
#pragma unroll
            for (int k = 0; k < KK; k++) {
                pu[k * DD + tid]       = acc0[k];
                pu[k * DD + tid + 256] = acc1[k];
                pu[k * DD + tid + 512] = acc2[k];
            }
            if (tid < KK) pmass[u * KK + tid] = massacc[tid];
        }
        __syncthreads();
    }
    __syncthreads();
}

// ---------------- reduce partials ----------------
__device__ void dev_reduce(const float* __restrict__ pupd, const float* __restrict__ pmass,
                           float* __restrict__ ub) {
    int tid = threadIdx.x;
    for (int r = blockIdx.x; r < SROWS; r += NB) {
        int b = r / KK, k = r % KK;
        float m = 0.f;
#pragma unroll
        for (int ch = 0; ch < NCH; ch++) m += pmass[(ch * BB + b) * KK + k];
        float inv = 1.0f / fmaxf(m, 1e-8f);
#pragma unroll
        for (int c = 0; c < 3; c++) {
            int d = tid + c * 256;
            float s = 0.f;
#pragma unroll
            for (int ch = 0; ch < NCH; ch++)
                s += pupd[(size_t)(ch * BB + b) * KK * DD + k * DD + d];
            ub[(size_t)r * DD + d] = s * inv;
        }
    }
}

// ---------------- tiny multi-head self-attention ----------------
__device__ void dev_blockattn(const float* __restrict__ qkv, float* __restrict__ obuf,
                              float* s_u) {
    float* qs = s_u;
    float* ks = s_u + 1152;
    float* vs = s_u + 2304;
    float* sc = s_u + 3456;
    float* at = s_u + 3600;
    int tid = threadIdx.x;
    for (int u = blockIdx.x; u < BB * HH; u += NB) {
        int b = u >> 3, h = u & 7;
        __syncthreads();
        for (int idx = tid; idx < KK * HD; idx += NT) {
            int r = idx / HD, c = idx % HD;
            size_t base = ((size_t)(b * KK + r)) * (3 * DD) + h * HD + c;
            qs[r * HD + c] = qkv[base];
            ks[r * HD + c] = qkv[base + DD];
            vs[r * HD + c] = qkv[base + 2 * DD];
        }
        __syncthreads();
        if (tid < 144) {
            int i = tid / KK, j = tid % KK;
            float s = 0.f;
#pragma unroll
            for (int d = 0; d < HD; d++) s = fmaf(qs[i * HD + d], ks[j * HD + d], s);
            sc[i * KK + j] = s * SCALE_HD;
        }
        __syncthreads();
        if (tid < 144) {
            int i = tid / KK, j = tid % KK;
            float mx = -1e30f;
#pragma unroll
            for (int jj = 0; jj < KK; jj++) mx = fmaxf(mx, sc[i * KK + jj]);
            float tot = 0.f;
#pragma unroll
            for (int jj = 0; jj < KK; jj++) tot += expf(sc[i * KK + jj] - mx);
            at[i * KK + j] = expf(sc[i * KK + j] - mx) / tot;
        }
        __syncthreads();
        for (int idx = tid; idx < KK * HD; idx += NT) {
            int r = idx / HD, d = idx % HD;
            float s = 0.f;
#pragma unroll
            for (int jj = 0; jj < KK; jj++) s = fmaf(at[r * KK + jj], vs[jj * HD + d], s);
            obuf[((size_t)(b * KK + r)) * DD + h * HD + d] = s;
        }
        __syncthreads();
    }
    __syncthreads();
}

// ---------------- transpose 768x768 ----------------
__device__ void dev_transpose(const float* __restrict__ in, float* __restrict__ out,
                              float* s_u) {
    float* tile = s_u;
    int tx = threadIdx.x & 31, ty = threadIdx.x >> 5;
    for (int tix = blockIdx.x; tix < 24 * 24; tix += NB) {
        int bx = (tix % 24) * 32, by = (tix / 24) * 32;
        __syncthreads();
#pragma unroll
        for (int dy = 0; dy < 4; dy++)
            tile[(ty + dy * 8) * 33 + tx] = in[(size_t)(by + ty + dy * 8) * DD + bx + tx];
        __syncthreads();
#pragma unroll
        for (int dy = 0; dy < 4; dy++)
            out[(size_t)(bx + ty + dy * 8) * DD + by + tx] = tile[tx * 33 + ty + dy * 8];
    }
    __syncthreads();
}

__device__ void dev_copy(float* __restrict__ dst, const float* __restrict__ src, int n4) {
    for (int i = blockIdx.x * NT + threadIdx.x; i < n4; i += NB * NT)
        ((float4*)dst)[i] = ((const float4*)src)[i];
}

// ---------------- the megakernel ----------------
__global__ __launch_bounds__(NT)
void mega_kernel(const float* features, const float* slots_init,
                 const float* nf_g, const float* nf_b,
                 const float* ns_g, const float* ns_b,
                 const float* Wq, const float* Wk, const float* Wv,
                 const float* mg, const float* mb,
                 const float* mW1, const float* mb1,
                 const float* mW2, const float* mb2,
                 const float* b_ln1g, const float* b_ln1b,
                 const float* b_Wqkv, const float* b_bqkv,
                 const float* b_Wo, const float* b_bo,
                 const float* b_ln2g, const float* b_ln2b,
                 const float* b_W1, const float* b_b1,
                 const float* b_W2, const float* b_b2,
                 float* out) {
    __shared__ __align__(16) float s_u[9728];

    dev_transpose(Wk, g_wkt, s_u);
    dev_ln(features, nullptr, nf_g, nf_b, g_fn, BNROWS);
    dev_copy(g_slots, slots_init, SROWS * DD / 4);
    gridbar();
    dev_gemm(Wq, g_wkt, nullptr, nullptr, g_wqk, DD, DD, DD, 0, s_u);
    gridbar();

    for (int t = 0; t < TT; t++) {
        const float* ln1g = b_ln1g + (size_t)t * DD;
        const float* ln1b = b_ln1b + (size_t)t * DD;
        const float* Wqkv = b_Wqkv + (size_t)t * DD * 3 * DD;
        const float* bqkv = b_bqkv + (size_t)t * 3 * DD;
        const float* Wo   = b_Wo   + (size_t)t * DD * DD;
        const float* bo   = b_bo   + (size_t)t * DD;
        const float* ln2g = b_ln2g + (size_t)t * DD;
        const float* ln2b = b_ln2b + (size_t)t * DD;
        const float* W1   = b_W1   + (size_t)t * DD * 4 * DD;
        const float* b1   = b_b1   + (size_t)t * 4 * DD;
        const float* W2   = b_W2   + (size_t)t * 4 * DD * DD;
        const float* b2   = b_b2   + (size_t)t * DD;

        dev_ln(g_slots, nullptr, ns_g, ns_b, g_sn, SROWS);
        gridbar();
        dev_gemm(g_sn, g_wqk, nullptr, nullptr, g_q, SROWS, DD, DD, 0, s_u);
        dev_ln(g_sn, nullptr, ln1g, ln1b, g_h1, SROWS);
        gridbar();
        dev_fused(g_q, g_fn, g_pupd, g_pmass, nullptr, 1, s_u);
        dev_gemm(g_h1, Wqkv, bqkv, nullptr, g_qkvb, SROWS, 3 * DD, DD, 0, s_u);
        gridbar();
        dev_reduce(g_pupd, g_pmass, g_ub);
        dev_blockattn(g_qkvb, g_ob, s_u);
        gridbar();
        dev_gemm(g_ub, Wv, nullptr, nullptr, g_upd, SROWS, DD, DD, 0, s_u);
        dev_gemm(g_ob, Wo, bo, g_sn, g_x1, SROWS, DD, DD, 0, s_u);
        gridbar();
        dev_ln(g_x1, nullptr, ln2g, ln2b, g_h2, SROWS);
        gridbar();
        dev_gemm(g_h2, W1, b1, nullptr, g_g1, SROWS, 4 * DD, DD, 1, s_u);
        gridbar();
        dev_gemm(g_g1, W2, b2, g_x1, g_x2, SROWS, DD, 4 * DD, 0, s_u);
        gridbar();
        dev_ln(g_upd, g_x2, mg, mb, g_h3, SROWS);
        gridbar();
        dev_gemm(g_h3, mW1, mb1, nullptr, g_g2, SROWS, 4 * DD, DD, 1, s_u);
        gridbar();
        dev_gemm(g_g2, mW2, mb2, g_slots, g_slots, SROWS, DD, 4 * DD, 0, s_u);
        gridbar();
    }

    dev_ln(g_slots, nullptr, ns_g, ns_b, g_sn, SROWS);
    gridbar();
    dev_gemm(g_sn, g_wqk, nullptr, nullptr, g_q, SROWS, DD, DD, 0, s_u);
    dev_copy(out, g_slots, SROWS * DD / 4);
    gridbar();
    dev_fused(g_q, g_fn, nullptr, nullptr, out + (size_t)SROWS * DD, 0, s_u);
}

// ---------------- host ----------------
extern "C" void kernel_launch(void* const* d_in, const int* in_sizes, int n_in,
                              void* d_out, int out_size) {
    const float* features  = (const float*)d_in[0];
    const float* slots_init= (const float*)d_in[1];
    const float* nf_g = (const float*)d_in[2];
    const float* nf_b = (const float*)d_in[3];
    const float* ns_g = (const float*)d_in[4];
    const float* ns_b = (const float*)d_in[5];
    const float* Wq   = (const float*)d_in[6];
    const float* Wk   = (const float*)d_in[7];
    const float* Wv   = (const float*)d_in[8];
    const float* mg   = (const float*)d_in[9];
    const float* mb   = (const float*)d_in[10];
    const float* mW1  = (const float*)d_in[11];
    const float* mb1  = (const float*)d_in[12];
    const float* mW2  = (const float*)d_in[13];
    const float* mb2  = (const float*)d_in[14];
    const float* b_ln1g = (const float*)d_in[15];
    const float* b_ln1b = (const float*)d_in[16];
    const float* b_Wqkv = (const float*)d_in[17];
    const float* b_bqkv = (const float*)d_in[18];
    const float* b_Wo   = (const float*)d_in[19];
    const float* b_bo   = (const float*)d_in[20];
    const float* b_ln2g = (const float*)d_in[21];
    const float* b_ln2b = (const float*)d_in[22];
    const float* b_W1   = (const float*)d_in[23];
    const float* b_b1   = (const float*)d_in[24];
    const float* b_W2   = (const float*)d_in[25];
    const float* b_b2   = (const float*)d_in[26];

    mega_kernel<<<NB, NT>>>(features, slots_init, nf_g, nf_b, ns_g, ns_b,
                            Wq, Wk, Wv, mg, mb, mW1, mb1, mW2, mb2,
                            b_ln1g, b_ln1b, b_Wqkv, b_bqkv, b_Wo, b_bo,
                            b_ln2g, b_ln2b, b_W1, b_b1, b_W2, b_b2,
                            (float*)d_out);
}